// round 1
// baseline (speedup 1.0000x reference)
#include <cuda_runtime.h>
#include <cuda_bf16.h>
#include <math.h>

// ---------------- problem constants ----------------
#define BATCH  2
#define SEQ    2048
#define EMB    1024
#define NHEAD  16
#define HDIM   64
#define M_TOT  (BATCH * SEQ)       // 4096
#define C3     (3 * EMB)           // 3072

// ---------------- scratch ----------------
__device__ float g_qkv[M_TOT * C3];   // 48 MB
__device__ float g_att[M_TOT * EMB];  // 16 MB

// ---------------- SGEMM: C = A(MxK) * B(KxN) + bias(N) ----------------
// A row-major, B row-major, 128x128x8 tiles, 256 threads, 8x8 per thread.
#define BM 128
#define BN 128
#define BK 8
#define TM 8
#define TN 8

__global__ __launch_bounds__(256, 2)
void sgemm_bias(const float* __restrict__ A, const float* __restrict__ B,
                const float* __restrict__ bias, float* __restrict__ C,
                int M, int N, int K)
{
    __shared__ float As[BK][BM];
    __shared__ float Bs[BK][BN];

    const int tid  = threadIdx.x;
    const int bRow = blockIdx.y;   // M tile
    const int bCol = blockIdx.x;   // N tile

    const int tCol = tid % (BN / TN);  // 0..15
    const int tRow = tid / (BN / TN);  // 0..15

    const float* Ab = A + (size_t)bRow * BM * K;
    const float* Bb = B + (size_t)bCol * BN;
    float*       Cb = C + (size_t)bRow * BM * N + (size_t)bCol * BN;

    // global-load indices
    const int aRow = tid >> 1;          // 0..127
    const int aCol = (tid & 1) * 4;     // 0 or 4
    const int bRowL = tid >> 5;         // 0..7
    const int bColL = (tid & 31) * 4;   // 0..124

    float acc[TM][TN];
#pragma unroll
    for (int i = 0; i < TM; i++)
#pragma unroll
        for (int j = 0; j < TN; j++) acc[i][j] = 0.f;

    float regM[TM], regN[TN];

    for (int k0 = 0; k0 < K; k0 += BK) {
        float4 av = *(const float4*)(Ab + (size_t)aRow * K + k0 + aCol);
        As[aCol + 0][aRow] = av.x;
        As[aCol + 1][aRow] = av.y;
        As[aCol + 2][aRow] = av.z;
        As[aCol + 3][aRow] = av.w;
        float4 bv = *(const float4*)(Bb + (size_t)(k0 + bRowL) * N + bColL);
        *(float4*)&Bs[bRowL][bColL] = bv;
        __syncthreads();

#pragma unroll
        for (int k = 0; k < BK; k++) {
#pragma unroll
            for (int i = 0; i < TM; i++) regM[i] = As[k][tRow * TM + i];
#pragma unroll
            for (int j = 0; j < TN; j++) regN[j] = Bs[k][tCol * TN + j];
#pragma unroll
            for (int i = 0; i < TM; i++)
#pragma unroll
                for (int j = 0; j < TN; j++)
                    acc[i][j] += regM[i] * regN[j];
        }
        __syncthreads();
    }

#pragma unroll
    for (int i = 0; i < TM; i++) {
        int row = tRow * TM + i;
#pragma unroll
        for (int j = 0; j < TN; j += 4) {
            int col = tCol * TN + j;
            float4 o;
            o.x = acc[i][j + 0] + bias[(size_t)bCol * BN + col + 0];
            o.y = acc[i][j + 1] + bias[(size_t)bCol * BN + col + 1];
            o.z = acc[i][j + 2] + bias[(size_t)bCol * BN + col + 2];
            o.w = acc[i][j + 3] + bias[(size_t)bCol * BN + col + 3];
            *(float4*)(Cb + (size_t)row * N + col) = o;
        }
    }
}

// ---------------- causal flash attention (fp32) ----------------
// grid: (T/64, NHEAD, BATCH), block 256 (8 warps).
// Each warp owns 8 query rows; each lane owns 2 score columns (j, j+32)
// and 2 output dims (d, d+32). 8-row register blocking in both inner loops
// keeps the smem-crossbar : FMA ratio at 10:16 warp-instructions.
#define ATQ 64
#define ATK 64

// smem layout sizes (floats)
#define QS_STRIDE 65
#define KS_STRIDE 65
#define PS_STRIDE 65
#define SM_Q  (ATQ * QS_STRIDE)
#define SM_K  (ATK * KS_STRIDE)
#define SM_V  (ATK * HDIM)
#define SM_P  (ATQ * PS_STRIDE)
#define ATT_SMEM_BYTES ((SM_Q + SM_K + SM_V + SM_P) * sizeof(float))

__global__ __launch_bounds__(256, 1)
void attn_kernel(const float* __restrict__ qkv, float* __restrict__ out)
{
    extern __shared__ float smem[];
    float (*Qs)[QS_STRIDE] = (float (*)[QS_STRIDE])(smem);
    float (*Ks)[KS_STRIDE] = (float (*)[KS_STRIDE])(smem + SM_Q);
    float (*Vs)[HDIM]      = (float (*)[HDIM])    (smem + SM_Q + SM_K);
    float (*Ps)[PS_STRIDE] = (float (*)[PS_STRIDE])(smem + SM_Q + SM_K + SM_V);

    const int qt   = blockIdx.x;
    const int h    = blockIdx.y;
    const int b    = blockIdx.z;
    const int tid  = threadIdx.x;
    const int warp = tid >> 5;
    const int lane = tid & 31;

    const int   hofs  = h * HDIM;
    const float scale = 0.125f;  // 1/sqrt(64)
    const float* base = qkv + (size_t)b * SEQ * C3;

    // load Q tile (rows qt*64..+63, dims hofs..+63) — 4 float4 per thread
    for (int i = tid; i < ATQ * (HDIM / 4); i += 256) {
        int r  = i >> 4;
        int c4 = (i & 15) * 4;
        float4 v = *(const float4*)(base + (size_t)(qt * ATQ + r) * C3 + hofs + c4);
        Qs[r][c4 + 0] = v.x; Qs[r][c4 + 1] = v.y;
        Qs[r][c4 + 2] = v.z; Qs[r][c4 + 3] = v.w;
    }

    float m_run[8], l_run[8], acc0[8], acc1[8];
#pragma unroll
    for (int i = 0; i < 8; i++) { m_run[i] = -1e30f; l_run[i] = 0.f; acc0[i] = 0.f; acc1[i] = 0.f; }

    const int j0 = lane, j1 = lane + 32;
    const int d0 = lane, d1 = lane + 32;
    const int rbase = warp * 8;

    for (int kt = 0; kt <= qt; kt++) {
        __syncthreads();  // K/V/Ps consumed by all warps (and Q ready on iter 0)
        // load K and V tiles
        for (int i = tid; i < ATK * (HDIM / 4); i += 256) {
            int r  = i >> 4;
            int c4 = (i & 15) * 4;
            const float* kp = base + (size_t)(kt * ATK + r) * C3 + EMB + hofs + c4;
            float4 kv = *(const float4*)kp;
            Ks[r][c4 + 0] = kv.x; Ks[r][c4 + 1] = kv.y;
            Ks[r][c4 + 2] = kv.z; Ks[r][c4 + 3] = kv.w;
            float4 vv = *(const float4*)(kp + EMB);
            *(float4*)&Vs[r][c4] = vv;
        }
        __syncthreads();

        const bool diag = (kt == qt);

        // ---- S = Q K^T (8 rows x 2 cols per lane) ----
        float s0[8], s1[8];
#pragma unroll
        for (int rr = 0; rr < 8; rr++) { s0[rr] = 0.f; s1[rr] = 0.f; }
#pragma unroll 8
        for (int d = 0; d < HDIM; d++) {
            float k0 = Ks[j0][d];
            float k1 = Ks[j1][d];
#pragma unroll
            for (int rr = 0; rr < 8; rr++) {
                float q = Qs[rbase + rr][d];
                s0[rr] += q * k0;
                s1[rr] += q * k1;
            }
        }

        // ---- online softmax per row ----
#pragma unroll
        for (int rr = 0; rr < 8; rr++) {
            float v0 = s0[rr] * scale;
            float v1 = s1[rr] * scale;
            if (diag) {
                int r = rbase + rr;
                if (j0 > r) v0 = -1e30f;
                if (j1 > r) v1 = -1e30f;
            }
            float mx = fmaxf(v0, v1);
#pragma unroll
            for (int o = 16; o > 0; o >>= 1)
                mx = fmaxf(mx, __shfl_xor_sync(0xffffffffu, mx, o));
            float m_new = fmaxf(m_run[rr], mx);
            float alpha = __expf(m_run[rr] - m_new);
            float p0 = __expf(v0 - m_new);
            float p1 = __expf(v1 - m_new);
            float ls = p0 + p1;
#pragma unroll
            for (int o = 16; o > 0; o >>= 1)
                ls += __shfl_xor_sync(0xffffffffu, ls, o);
            l_run[rr] = l_run[rr] * alpha + ls;
            m_run[rr] = m_new;
            acc0[rr] *= alpha;
            acc1[rr] *= alpha;
            Ps[rbase + rr][j0] = p0;
            Ps[rbase + rr][j1] = p1;
        }
        __syncwarp();

        // ---- O += P V (8 rows x 2 dims per lane) ----
#pragma unroll 8
        for (int j = 0; j < ATK; j++) {
            float v0 = Vs[j][d0];
            float v1 = Vs[j][d1];
#pragma unroll
            for (int rr = 0; rr < 8; rr++) {
                float p = Ps[rbase + rr][j];
                acc0[rr] += p * v0;
                acc1[rr] += p * v1;
            }
        }
    }

    // epilogue: out[b, qt*64+r, h*64+d] (layout [B,T,C])
#pragma unroll
    for (int rr = 0; rr < 8; rr++) {
        int r = rbase + rr;
        float inv = 1.f / l_run[rr];
        size_t o = ((size_t)b * SEQ + qt * ATQ + r) * EMB + hofs;
        out[o + d0] = acc0[rr] * inv;
        out[o + d1] = acc1[rr] * inv;
    }
}

// ---------------- launcher ----------------
extern "C" void kernel_launch(void* const* d_in, const int* in_sizes, int n_in,
                              void* d_out, int out_size)
{
    const float* x     = (const float*)d_in[0];
    const float* Wqkv  = (const float*)d_in[1];
    const float* bqkv  = (const float*)d_in[2];
    const float* Wproj = (const float*)d_in[3];
    const float* bproj = (const float*)d_in[4];
    float* out = (float*)d_out;

    float* qkv_ptr = nullptr;
    float* att_ptr = nullptr;
    cudaGetSymbolAddress((void**)&qkv_ptr, g_qkv);
    cudaGetSymbolAddress((void**)&att_ptr, g_att);

    cudaFuncSetAttribute(attn_kernel,
                         cudaFuncAttributeMaxDynamicSharedMemorySize,
                         (int)ATT_SMEM_BYTES);

    // 1) qkv = x @ W_qkv + b_qkv      [4096,1024] x [1024,3072]
    sgemm_bias<<<dim3(C3 / BN, M_TOT / BM), 256>>>(x, Wqkv, bqkv, qkv_ptr,
                                                   M_TOT, C3, EMB);
    // 2) causal attention             -> [B,T,C]
    attn_kernel<<<dim3(SEQ / ATQ, NHEAD, BATCH), 256, ATT_SMEM_BYTES>>>(qkv_ptr, att_ptr);
    // 3) out = att @ W_proj + b_proj  [4096,1024] x [1024,1024]
    sgemm_bias<<<dim3(EMB / BN, M_TOT / BM), 256>>>(att_ptr, Wproj, bproj, out,
                                                    M_TOT, EMB, EMB);
}

// round 3
// speedup vs baseline: 1.5820x; 1.5820x over previous
#include <cuda_runtime.h>
#include <cuda_bf16.h>
#include <math.h>
#include <stdint.h>

// ---------------- problem constants ----------------
#define BATCH  2
#define SEQ    2048
#define EMB    1024
#define NHEAD  16
#define HDIM   64
#define M_TOT  (BATCH * SEQ)       // 4096
#define C3     (3 * EMB)           // 3072
#define KDIM   1024

// ---------------- scratch ----------------
__device__ float g_qkv[M_TOT * C3];     // 48 MB
__device__ float g_att[M_TOT * EMB];    // 16 MB  (attention out, tf32-rounded)
__device__ float g_xr[M_TOT * EMB];     // 16 MB  (x, tf32-rounded)
__device__ float g_Wqkv_r[EMB * C3];    // 12 MB  (W_qkv, tf32-rounded)
__device__ float g_Wproj_r[EMB * EMB];  //  4 MB  (W_proj, tf32-rounded)

// ================= helpers =================
__device__ __forceinline__ uint32_t smem_u32(const void* p) {
    uint32_t a;
    asm("{ .reg .u64 t; cvta.to.shared.u64 t, %1; cvt.u32.u64 %0, t; }" : "=r"(a) : "l"(p));
    return a;
}
__device__ __forceinline__ float tf32r(float x) {
    uint32_t r;
    asm("cvt.rna.tf32.f32 %0, %1;" : "=r"(r) : "f"(x));
    return __uint_as_float(r);
}
__device__ __forceinline__ void cpa16(uint32_t saddr, const void* g) {
    asm volatile("cp.async.cg.shared.global [%0], [%1], 16;" :: "r"(saddr), "l"(g));
}
#define CP_COMMIT()  asm volatile("cp.async.commit_group;")
#define CP_WAIT(n)   asm volatile("cp.async.wait_group %0;" :: "n"(n))

__device__ __forceinline__ void mma_tf32(float* d, const uint32_t* a, const uint32_t* b) {
    asm volatile(
        "mma.sync.aligned.m16n8k8.row.col.f32.tf32.tf32.f32 "
        "{%0,%1,%2,%3}, {%4,%5,%6,%7}, {%8,%9}, {%0,%1,%2,%3};"
        : "+f"(d[0]), "+f"(d[1]), "+f"(d[2]), "+f"(d[3])
        : "r"(a[0]), "r"(a[1]), "r"(a[2]), "r"(a[3]), "r"(b[0]), "r"(b[1]));
}

// ================= tf32 mma.sync GEMM =================
// C[M,N] = A[M,K] @ B[K,N] + bias.  A,B row-major, pre-rounded to tf32.
// CTA tile 128x128, BK=16, 256 threads = 8 warps (2 M x 4 N), warp tile 64x32.
#define BM 128
#define BN 128
#define BK 16
#define NIT (KDIM / BK)          // 64
#define A_PAD 20                 // floats per A smem row  (bank = 4g+q -> conflict-free)
#define B_PAD 136                // floats per B smem row  (bank = 8q+g -> conflict-free)
#define A_STAGE (BM * A_PAD)     // 2560 floats
#define B_STAGE (BK * B_PAD)     // 2176 floats

__global__ void __launch_bounds__(256, 1)
gemm_tf32_mma(const float* __restrict__ A, const float* __restrict__ B,
              const float* __restrict__ bias, float* __restrict__ C, int N)
{
    __shared__ float sA[2][A_STAGE];
    __shared__ float sB[2][B_STAGE];

    const int tid   = threadIdx.x;
    const int wid   = tid >> 5;
    const int lane  = tid & 31;
    const int g     = lane >> 2;      // 0..7
    const int q     = lane & 3;       // 0..3
    const int warpM = wid >> 2;       // 0..1
    const int warpN = wid & 3;        // 0..3
    const int m0    = blockIdx.y * BM;
    const int n0    = blockIdx.x * BN;

    const uint32_t sA0 = smem_u32(&sA[0][0]);
    const uint32_t sB0 = smem_u32(&sB[0][0]);

    // global->smem load (one BK chunk): A 512 chunks of 16B, B 512 chunks of 16B
    const int arow = (tid >> 2) | 0;           // reuse below with j offset
    auto load_tiles = [&](int it, int s) {
        const int k0 = it * BK;
        const uint32_t aBase = sA0 + s * A_STAGE * 4;
        const uint32_t bBase = sB0 + s * B_STAGE * 4;
#pragma unroll
        for (int j = 0; j < 2; j++) {
            int c = tid + j * 256;
            int r = c >> 2, seg = c & 3;
            cpa16(aBase + (r * A_PAD + seg * 4) * 4,
                  A + (size_t)(m0 + r) * KDIM + k0 + seg * 4);
        }
#pragma unroll
        for (int j = 0; j < 2; j++) {
            int c = tid + j * 256;
            int r = c >> 5, seg = c & 31;
            cpa16(bBase + (r * B_PAD + seg * 4) * 4,
                  B + (size_t)(k0 + r) * N + n0 + seg * 4);
        }
        CP_COMMIT();
    };

    float acc[4][4][4];
#pragma unroll
    for (int i = 0; i < 4; i++)
#pragma unroll
        for (int j = 0; j < 4; j++)
#pragma unroll
            for (int v = 0; v < 4; v++) acc[i][j][v] = 0.f;

    load_tiles(0, 0);

    for (int it = 0; it < NIT; it++) {
        const int s = it & 1;
        if (it + 1 < NIT) { load_tiles(it + 1, s ^ 1); CP_WAIT(1); }
        else              { CP_WAIT(0); }
        __syncthreads();

        const float* As = &sA[s][0];
        const float* Bs = &sB[s][0];
        const int mb = warpM * 64;
        const int nb = warpN * 32;

#pragma unroll
        for (int kk = 0; kk < 2; kk++) {
            const int k = kk * 8;
            uint32_t af[4][4], bf[4][2];
#pragma unroll
            for (int mt = 0; mt < 4; mt++) {
                const int rb = mb + mt * 16;
                af[mt][0] = __float_as_uint(As[(rb + g)     * A_PAD + k + q]);
                af[mt][1] = __float_as_uint(As[(rb + g + 8) * A_PAD + k + q]);
                af[mt][2] = __float_as_uint(As[(rb + g)     * A_PAD + k + q + 4]);
                af[mt][3] = __float_as_uint(As[(rb + g + 8) * A_PAD + k + q + 4]);
            }
#pragma unroll
            for (int nt = 0; nt < 4; nt++) {
                const int cb = nb + nt * 8;
                bf[nt][0] = __float_as_uint(Bs[(k + q)     * B_PAD + cb + g]);
                bf[nt][1] = __float_as_uint(Bs[(k + q + 4) * B_PAD + cb + g]);
            }
#pragma unroll
            for (int mt = 0; mt < 4; mt++)
#pragma unroll
                for (int nt = 0; nt < 4; nt++)
                    mma_tf32(acc[mt][nt], af[mt], bf[nt]);
        }
        __syncthreads();
    }

    // epilogue
#pragma unroll
    for (int mt = 0; mt < 4; mt++) {
        const int rm = m0 + warpM * 64 + mt * 16 + g;
#pragma unroll
        for (int nt = 0; nt < 4; nt++) {
            const int cn = n0 + warpN * 32 + nt * 8 + 2 * q;
            float2 o0, o1;
            o0.x = acc[mt][nt][0] + bias[cn];
            o0.y = acc[mt][nt][1] + bias[cn + 1];
            o1.x = acc[mt][nt][2] + bias[cn];
            o1.y = acc[mt][nt][3] + bias[cn + 1];
            *(float2*)(C + (size_t)rm * N + cn)       = o0;
            *(float2*)(C + (size_t)(rm + 8) * N + cn) = o1;
        }
    }
}

// ================= rounding helper =================
__global__ void round_tf32_kernel(const float* __restrict__ in, float* __restrict__ out, int n4)
{
    int i = blockIdx.x * blockDim.x + threadIdx.x;
    if (i < n4) {
        float4 v = ((const float4*)in)[i];
        v.x = tf32r(v.x); v.y = tf32r(v.y); v.z = tf32r(v.z); v.w = tf32r(v.w);
        ((float4*)out)[i] = v;
    }
}

// ---------------- causal flash attention (fp32) ----------------
#define ATQ 64
#define ATK 64
#define QS_STRIDE 65
#define KS_STRIDE 65
#define PS_STRIDE 65
#define SM_Q  (ATQ * QS_STRIDE)
#define SM_K  (ATK * KS_STRIDE)
#define SM_V  (ATK * HDIM)
#define SM_P  (ATQ * PS_STRIDE)
#define ATT_SMEM_BYTES ((SM_Q + SM_K + SM_V + SM_P) * sizeof(float))

__global__ __launch_bounds__(256, 1)
void attn_kernel(const float* __restrict__ qkv, float* __restrict__ out)
{
    extern __shared__ float smem[];
    float (*Qs)[QS_STRIDE] = (float (*)[QS_STRIDE])(smem);
    float (*Ks)[KS_STRIDE] = (float (*)[KS_STRIDE])(smem + SM_Q);
    float (*Vs)[HDIM]      = (float (*)[HDIM])    (smem + SM_Q + SM_K);
    float (*Ps)[PS_STRIDE] = (float (*)[PS_STRIDE])(smem + SM_Q + SM_K + SM_V);

    const int qt   = blockIdx.x;
    const int h    = blockIdx.y;
    const int b    = blockIdx.z;
    const int tid  = threadIdx.x;
    const int warp = tid >> 5;
    const int lane = tid & 31;

    const int   hofs  = h * HDIM;
    const float scale = 0.125f;
    const float* base = qkv + (size_t)b * SEQ * C3;

    for (int i = tid; i < ATQ * (HDIM / 4); i += 256) {
        int r  = i >> 4;
        int c4 = (i & 15) * 4;
        float4 v = *(const float4*)(base + (size_t)(qt * ATQ + r) * C3 + hofs + c4);
        Qs[r][c4 + 0] = v.x; Qs[r][c4 + 1] = v.y;
        Qs[r][c4 + 2] = v.z; Qs[r][c4 + 3] = v.w;
    }

    float m_run[8], l_run[8], acc0[8], acc1[8];
#pragma unroll
    for (int i = 0; i < 8; i++) { m_run[i] = -1e30f; l_run[i] = 0.f; acc0[i] = 0.f; acc1[i] = 0.f; }

    const int j0 = lane, j1 = lane + 32;
    const int d0 = lane, d1 = lane + 32;
    const int rbase = warp * 8;

    for (int kt = 0; kt <= qt; kt++) {
        __syncthreads();
        for (int i = tid; i < ATK * (HDIM / 4); i += 256) {
            int r  = i >> 4;
            int c4 = (i & 15) * 4;
            const float* kp = base + (size_t)(kt * ATK + r) * C3 + EMB + hofs + c4;
            float4 kv = *(const float4*)kp;
            Ks[r][c4 + 0] = kv.x; Ks[r][c4 + 1] = kv.y;
            Ks[r][c4 + 2] = kv.z; Ks[r][c4 + 3] = kv.w;
            float4 vv = *(const float4*)(kp + EMB);
            *(float4*)&Vs[r][c4] = vv;
        }
        __syncthreads();

        const bool diag = (kt == qt);

        float s0[8], s1[8];
#pragma unroll
        for (int rr = 0; rr < 8; rr++) { s0[rr] = 0.f; s1[rr] = 0.f; }
#pragma unroll 8
        for (int d = 0; d < HDIM; d++) {
            float k0 = Ks[j0][d];
            float k1 = Ks[j1][d];
#pragma unroll
            for (int rr = 0; rr < 8; rr++) {
                float qv = Qs[rbase + rr][d];
                s0[rr] += qv * k0;
                s1[rr] += qv * k1;
            }
        }

#pragma unroll
        for (int rr = 0; rr < 8; rr++) {
            float v0 = s0[rr] * scale;
            float v1 = s1[rr] * scale;
            if (diag) {
                int r = rbase + rr;
                if (j0 > r) v0 = -1e30f;
                if (j1 > r) v1 = -1e30f;
            }
            float mx = fmaxf(v0, v1);
#pragma unroll
            for (int o = 16; o > 0; o >>= 1)
                mx = fmaxf(mx, __shfl_xor_sync(0xffffffffu, mx, o));
            float m_new = fmaxf(m_run[rr], mx);
            float alpha = __expf(m_run[rr] - m_new);
            float p0 = __expf(v0 - m_new);
            float p1 = __expf(v1 - m_new);
            float ls = p0 + p1;
#pragma unroll
            for (int o = 16; o > 0; o >>= 1)
                ls += __shfl_xor_sync(0xffffffffu, ls, o);
            l_run[rr] = l_run[rr] * alpha + ls;
            m_run[rr] = m_new;
            acc0[rr] *= alpha;
            acc1[rr] *= alpha;
            Ps[rbase + rr][j0] = p0;
            Ps[rbase + rr][j1] = p1;
        }
        __syncwarp();

#pragma unroll 8
        for (int j = 0; j < ATK; j++) {
            float v0 = Vs[j][d0];
            float v1 = Vs[j][d1];
#pragma unroll
            for (int rr = 0; rr < 8; rr++) {
                float p = Ps[rbase + rr][j];
                acc0[rr] += p * v0;
                acc1[rr] += p * v1;
            }
        }
    }

    // epilogue: tf32-round (feeds the proj tf32 GEMM)
#pragma unroll
    for (int rr = 0; rr < 8; rr++) {
        int r = rbase + rr;
        float inv = 1.f / l_run[rr];
        size_t o = ((size_t)b * SEQ + qt * ATQ + r) * EMB + hofs;
        out[o + d0] = tf32r(acc0[rr] * inv);
        out[o + d1] = tf32r(acc1[rr] * inv);
    }
}

// ---------------- launcher ----------------
extern "C" void kernel_launch(void* const* d_in, const int* in_sizes, int n_in,
                              void* d_out, int out_size)
{
    const float* x     = (const float*)d_in[0];
    const float* Wqkv  = (const float*)d_in[1];
    const float* bqkv  = (const float*)d_in[2];
    const float* Wproj = (const float*)d_in[3];
    const float* bproj = (const float*)d_in[4];
    float* out = (float*)d_out;

    float *qkv_p, *att_p, *xr_p, *wq_p, *wp_p;
    cudaGetSymbolAddress((void**)&qkv_p, g_qkv);
    cudaGetSymbolAddress((void**)&att_p, g_att);
    cudaGetSymbolAddress((void**)&xr_p,  g_xr);
    cudaGetSymbolAddress((void**)&wq_p,  g_Wqkv_r);
    cudaGetSymbolAddress((void**)&wp_p,  g_Wproj_r);

    cudaFuncSetAttribute(attn_kernel, cudaFuncAttributeMaxDynamicSharedMemorySize,
                         (int)ATT_SMEM_BYTES);

    // 0) tf32-round inputs/weights (elementwise; no transpose needed)
    round_tf32_kernel<<<(M_TOT * EMB / 4 + 255) / 256, 256>>>(x, xr_p, M_TOT * EMB / 4);
    round_tf32_kernel<<<(EMB * C3 / 4 + 255) / 256, 256>>>(Wqkv, wq_p, EMB * C3 / 4);
    round_tf32_kernel<<<(EMB * EMB / 4 + 255) / 256, 256>>>(Wproj, wp_p, EMB * EMB / 4);

    // 1) qkv = x @ W_qkv + b_qkv   (tf32 mma.sync)
    gemm_tf32_mma<<<dim3(C3 / BN, M_TOT / BM), 256>>>(xr_p, wq_p, bqkv, qkv_p, C3);

    // 2) causal attention (fp32)
    attn_kernel<<<dim3(SEQ / ATQ, NHEAD, BATCH), 256, ATT_SMEM_BYTES>>>(qkv_p, att_p);

    // 3) out = att @ W_proj + b_proj  (tf32 mma.sync)
    gemm_tf32_mma<<<dim3(EMB / BN, M_TOT / BM), 256>>>(att_p, wp_p, bproj, out, EMB);
}

// round 4
// speedup vs baseline: 2.7503x; 1.7386x over previous
#include <cuda_runtime.h>
#include <cuda_bf16.h>
#include <math.h>
#include <stdint.h>

// ---------------- problem constants ----------------
#define BATCH  2
#define SEQ    2048
#define EMB    1024
#define NHEAD  16
#define HDIM   64
#define M_TOT  (BATCH * SEQ)       // 4096
#define C3     (3 * EMB)           // 3072
#define KDIM   1024

// ---------------- scratch ----------------
__device__ float g_qkv[M_TOT * C3];     // 48 MB
__device__ float g_att[M_TOT * EMB];    // 16 MB  (attention out, tf32-rounded)
__device__ float g_xr[M_TOT * EMB];     // 16 MB  (x, tf32-rounded)
__device__ float g_Wqkv_r[EMB * C3];    // 12 MB
__device__ float g_Wproj_r[EMB * EMB];  //  4 MB

// ================= helpers =================
__device__ __forceinline__ uint32_t smem_u32(const void* p) {
    uint32_t a;
    asm("{ .reg .u64 t; cvta.to.shared.u64 t, %1; cvt.u32.u64 %0, t; }" : "=r"(a) : "l"(p));
    return a;
}
__device__ __forceinline__ float tf32r(float x) {
    uint32_t r;
    asm("cvt.rna.tf32.f32 %0, %1;" : "=r"(r) : "f"(x));
    return __uint_as_float(r);
}
__device__ __forceinline__ void cpa16(uint32_t saddr, const void* g) {
    asm volatile("cp.async.cg.shared.global [%0], [%1], 16;" :: "r"(saddr), "l"(g));
}
#define CP_COMMIT()  asm volatile("cp.async.commit_group;")
#define CP_WAIT(n)   asm volatile("cp.async.wait_group %0;" :: "n"(n))

__device__ __forceinline__ void mma_tf32(float* d, const uint32_t* a, const uint32_t* b) {
    asm volatile(
        "mma.sync.aligned.m16n8k8.row.col.f32.tf32.tf32.f32 "
        "{%0,%1,%2,%3}, {%4,%5,%6,%7}, {%8,%9}, {%0,%1,%2,%3};"
        : "+f"(d[0]), "+f"(d[1]), "+f"(d[2]), "+f"(d[3])
        : "r"(a[0]), "r"(a[1]), "r"(a[2]), "r"(a[3]), "r"(b[0]), "r"(b[1]));
}
__device__ __forceinline__ void mma_bf16(float* d, uint32_t a0, uint32_t a1,
                                         uint32_t a2, uint32_t a3,
                                         uint32_t b0, uint32_t b1) {
    asm volatile(
        "mma.sync.aligned.m16n8k16.row.col.f32.bf16.bf16.f32 "
        "{%0,%1,%2,%3}, {%4,%5,%6,%7}, {%8,%9}, {%0,%1,%2,%3};"
        : "+f"(d[0]), "+f"(d[1]), "+f"(d[2]), "+f"(d[3])
        : "r"(a0), "r"(a1), "r"(a2), "r"(a3), "r"(b0), "r"(b1));
}
// pack two f32 -> bf16x2 word, low = e, high = o
__device__ __forceinline__ uint32_t pack_bf16x2(float e, float o) {
    uint32_t r;
    asm("cvt.rn.bf16x2.f32 %0, %1, %2;" : "=r"(r) : "f"(o), "f"(e));
    return r;
}
// hi/lo split store: hi word + residual-lo word
__device__ __forceinline__ void split_store(uint32_t* hiA, uint32_t* loA, int idx,
                                            float e, float o) {
    uint32_t whi = pack_bf16x2(e, o);
    float he = __uint_as_float(whi << 16);
    float ho = __uint_as_float(whi & 0xFFFF0000u);
    hiA[idx] = whi;
    loA[idx] = pack_bf16x2(e - he, o - ho);
}

// ================= tf32 mma.sync GEMM (unchanged, round-3 proven) =================
#define BM 128
#define BN 128
#define BK 16
#define NIT (KDIM / BK)
#define A_PAD 20
#define B_PAD 136
#define A_STAGE (BM * A_PAD)
#define B_STAGE (BK * B_PAD)

__global__ void __launch_bounds__(256, 1)
gemm_tf32_mma(const float* __restrict__ A, const float* __restrict__ B,
              const float* __restrict__ bias, float* __restrict__ C, int N)
{
    __shared__ float sA[2][A_STAGE];
    __shared__ float sB[2][B_STAGE];

    const int tid   = threadIdx.x;
    const int wid   = tid >> 5;
    const int lane  = tid & 31;
    const int g     = lane >> 2;
    const int q     = lane & 3;
    const int warpM = wid >> 2;
    const int warpN = wid & 3;
    const int m0    = blockIdx.y * BM;
    const int n0    = blockIdx.x * BN;

    const uint32_t sA0 = smem_u32(&sA[0][0]);
    const uint32_t sB0 = smem_u32(&sB[0][0]);

    auto load_tiles = [&](int it, int s) {
        const int k0 = it * BK;
        const uint32_t aBase = sA0 + s * A_STAGE * 4;
        const uint32_t bBase = sB0 + s * B_STAGE * 4;
#pragma unroll
        for (int j = 0; j < 2; j++) {
            int c = tid + j * 256;
            int r = c >> 2, seg = c & 3;
            cpa16(aBase + (r * A_PAD + seg * 4) * 4,
                  A + (size_t)(m0 + r) * KDIM + k0 + seg * 4);
        }
#pragma unroll
        for (int j = 0; j < 2; j++) {
            int c = tid + j * 256;
            int r = c >> 5, seg = c & 31;
            cpa16(bBase + (r * B_PAD + seg * 4) * 4,
                  B + (size_t)(k0 + r) * N + n0 + seg * 4);
        }
        CP_COMMIT();
    };

    float acc[4][4][4];
#pragma unroll
    for (int i = 0; i < 4; i++)
#pragma unroll
        for (int j = 0; j < 4; j++)
#pragma unroll
            for (int v = 0; v < 4; v++) acc[i][j][v] = 0.f;

    load_tiles(0, 0);

    for (int it = 0; it < NIT; it++) {
        const int s = it & 1;
        if (it + 1 < NIT) { load_tiles(it + 1, s ^ 1); CP_WAIT(1); }
        else              { CP_WAIT(0); }
        __syncthreads();

        const float* As = &sA[s][0];
        const float* Bs = &sB[s][0];
        const int mb = warpM * 64;
        const int nb = warpN * 32;

#pragma unroll
        for (int kk = 0; kk < 2; kk++) {
            const int k = kk * 8;
            uint32_t af[4][4], bf[4][2];
#pragma unroll
            for (int mt = 0; mt < 4; mt++) {
                const int rb = mb + mt * 16;
                af[mt][0] = __float_as_uint(As[(rb + g)     * A_PAD + k + q]);
                af[mt][1] = __float_as_uint(As[(rb + g + 8) * A_PAD + k + q]);
                af[mt][2] = __float_as_uint(As[(rb + g)     * A_PAD + k + q + 4]);
                af[mt][3] = __float_as_uint(As[(rb + g + 8) * A_PAD + k + q + 4]);
            }
#pragma unroll
            for (int nt = 0; nt < 4; nt++) {
                const int cb = nb + nt * 8;
                bf[nt][0] = __float_as_uint(Bs[(k + q)     * B_PAD + cb + g]);
                bf[nt][1] = __float_as_uint(Bs[(k + q + 4) * B_PAD + cb + g]);
            }
#pragma unroll
            for (int mt = 0; mt < 4; mt++)
#pragma unroll
                for (int nt = 0; nt < 4; nt++)
                    mma_tf32(acc[mt][nt], af[mt], bf[nt]);
        }
        __syncthreads();
    }

#pragma unroll
    for (int mt = 0; mt < 4; mt++) {
        const int rm = m0 + warpM * 64 + mt * 16 + g;
#pragma unroll
        for (int nt = 0; nt < 4; nt++) {
            const int cn = n0 + warpN * 32 + nt * 8 + 2 * q;
            float2 o0, o1;
            o0.x = acc[mt][nt][0] + bias[cn];
            o0.y = acc[mt][nt][1] + bias[cn + 1];
            o1.x = acc[mt][nt][2] + bias[cn];
            o1.y = acc[mt][nt][3] + bias[cn + 1];
            *(float2*)(C + (size_t)rm * N + cn)       = o0;
            *(float2*)(C + (size_t)(rm + 8) * N + cn) = o1;
        }
    }
}

// ================= rounding helper =================
__global__ void round_tf32_kernel(const float* __restrict__ in, float* __restrict__ out, int n4)
{
    int i = blockIdx.x * blockDim.x + threadIdx.x;
    if (i < n4) {
        float4 v = ((const float4*)in)[i];
        v.x = tf32r(v.x); v.y = tf32r(v.y); v.z = tf32r(v.z); v.w = tf32r(v.w);
        ((float4*)out)[i] = v;
    }
}

// ================= tensor-core causal flash attention (bf16x3) =================
// Q tile 128 rows, K tile 64, 8 warps x 16 rows. smem rows padded to 36 words.
#define ROWW 36
#define SM_QHI 0
#define SM_QLO (SM_QHI + 128 * ROWW)
#define SM_KHI (SM_QLO + 128 * ROWW)
#define SM_KLO (SM_KHI + 64 * ROWW)
#define SM_VHI (SM_KLO + 64 * ROWW)
#define SM_VLO (SM_VHI + 64 * ROWW)
#define ATT_SMEM_WORDS (SM_VLO + 64 * ROWW)
#define ATT_SMEM_BYTES (ATT_SMEM_WORDS * 4)

__global__ void __launch_bounds__(256)
attn_mma_kernel(const float* __restrict__ qkv, float* __restrict__ out)
{
    extern __shared__ uint32_t sbuf[];
    uint32_t* Qhi = sbuf + SM_QHI;
    uint32_t* Qlo = sbuf + SM_QLO;
    uint32_t* Khi = sbuf + SM_KHI;
    uint32_t* Klo = sbuf + SM_KLO;
    uint32_t* Vhi = sbuf + SM_VHI;
    uint32_t* Vlo = sbuf + SM_VLO;

    const int qt   = (SEQ / 128 - 1) - blockIdx.x;   // heavy tiles first
    const int h    = blockIdx.y;
    const int b    = blockIdx.z;
    const int tid  = threadIdx.x;
    const int w    = tid >> 5;
    const int lane = tid & 31;
    const int g    = lane >> 2;     // groupID
    const int q    = lane & 3;      // thread-in-group

    const int hofs = h * HDIM;
    const float* base = qkv + (size_t)b * SEQ * C3;

    // --- load Q tile (scaled by 1/8), split to bf16 hi/lo, k-pair packed ---
    for (int i = tid; i < 128 * 32; i += 256) {
        int r = i >> 5, wd = i & 31;
        float2 v = *(const float2*)(base + (size_t)(qt * 128 + r) * C3 + hofs + 2 * wd);
        split_store(Qhi, Qlo, r * ROWW + wd, v.x * 0.125f, v.y * 0.125f);
    }

    float o[8][4];
#pragma unroll
    for (int t = 0; t < 8; t++)
#pragma unroll
        for (int v = 0; v < 4; v++) o[t][v] = 0.f;
    float m0 = -1e30f, m1 = -1e30f, l0 = 0.f, l1 = 0.f;

    const int rb   = w * 16;
    const int row0 = qt * 128 + rb + g;   // global seq row (c0/c1)
    const int row1 = row0 + 8;
    const int kend = 2 * qt + 2;

    for (int kt = 0; kt < kend; kt++) {
        __syncthreads();
        // K tile: [64 keys][32 d-pair words]
        for (int i = tid; i < 64 * 32; i += 256) {
            int r = i >> 5, wd = i & 31;
            float2 v = *(const float2*)(base + (size_t)(kt * 64 + r) * C3 + EMB + hofs + 2 * wd);
            split_store(Khi, Klo, r * ROWW + wd, v.x, v.y);
        }
        // V tile transposed: Vt[d][key-pair word]
        for (int i = tid; i < 64 * 32; i += 256) {
            int d = i & 63, cw = i >> 6;
            const float* vp = base + (size_t)(kt * 64 + 2 * cw) * C3 + 2 * EMB + hofs + d;
            split_store(Vhi, Vlo, d * ROWW + cw, vp[0], vp[C3]);
        }
        __syncthreads();

        if (kt * 64 > qt * 128 + rb + 15) continue;   // warp fully masked

        // ---- S = (Q/8) K^T : 8 n-tiles, 4 k16 chunks, 3 passes ----
        float s[8][4];
#pragma unroll
        for (int t = 0; t < 8; t++)
#pragma unroll
            for (int v = 0; v < 4; v++) s[t][v] = 0.f;

#pragma unroll
        for (int j = 0; j < 4; j++) {
            const int q0 = (rb + g) * ROWW + 8 * j + q;
            const int q1 = (rb + g + 8) * ROWW + 8 * j + q;
            uint32_t qh0 = Qhi[q0], qh1 = Qhi[q1], qh2 = Qhi[q0 + 4], qh3 = Qhi[q1 + 4];
            uint32_t ql0 = Qlo[q0], ql1 = Qlo[q1], ql2 = Qlo[q0 + 4], ql3 = Qlo[q1 + 4];
#pragma unroll
            for (int t = 0; t < 8; t++) {
                const int kr = (8 * t + g) * ROWW + 8 * j + q;
                uint32_t kh0 = Khi[kr], kh1 = Khi[kr + 4];
                uint32_t kl0 = Klo[kr], kl1 = Klo[kr + 4];
                mma_bf16(s[t], qh0, qh1, qh2, qh3, kh0, kh1);
                mma_bf16(s[t], qh0, qh1, qh2, qh3, kl0, kl1);
                mma_bf16(s[t], ql0, ql1, ql2, ql3, kh0, kh1);
            }
        }

        // ---- causal mask (diagonal region only) ----
        if (kt >= 2 * qt) {
#pragma unroll
            for (int t = 0; t < 8; t++) {
                int col = kt * 64 + 8 * t + 2 * q;
                if (col     > row0) s[t][0] = -1e30f;
                if (col + 1 > row0) s[t][1] = -1e30f;
                if (col     > row1) s[t][2] = -1e30f;
                if (col + 1 > row1) s[t][3] = -1e30f;
            }
        }

        // ---- online softmax (rows row0, row1) ----
        float mx0 = -1e30f, mx1 = -1e30f;
#pragma unroll
        for (int t = 0; t < 8; t++) {
            mx0 = fmaxf(mx0, fmaxf(s[t][0], s[t][1]));
            mx1 = fmaxf(mx1, fmaxf(s[t][2], s[t][3]));
        }
        mx0 = fmaxf(mx0, __shfl_xor_sync(0xffffffffu, mx0, 1));
        mx0 = fmaxf(mx0, __shfl_xor_sync(0xffffffffu, mx0, 2));
        mx1 = fmaxf(mx1, __shfl_xor_sync(0xffffffffu, mx1, 1));
        mx1 = fmaxf(mx1, __shfl_xor_sync(0xffffffffu, mx1, 2));

        float mn0 = fmaxf(m0, mx0), mn1 = fmaxf(m1, mx1);
        float a0 = __expf(m0 - mn0), a1 = __expf(m1 - mn1);
        float sum0 = 0.f, sum1 = 0.f;
#pragma unroll
        for (int t = 0; t < 8; t++) {
            s[t][0] = __expf(s[t][0] - mn0);
            s[t][1] = __expf(s[t][1] - mn0);
            s[t][2] = __expf(s[t][2] - mn1);
            s[t][3] = __expf(s[t][3] - mn1);
            sum0 += s[t][0] + s[t][1];
            sum1 += s[t][2] + s[t][3];
        }
        sum0 += __shfl_xor_sync(0xffffffffu, sum0, 1);
        sum0 += __shfl_xor_sync(0xffffffffu, sum0, 2);
        sum1 += __shfl_xor_sync(0xffffffffu, sum1, 1);
        sum1 += __shfl_xor_sync(0xffffffffu, sum1, 2);
        l0 = l0 * a0 + sum0;
        l1 = l1 * a1 + sum1;
        m0 = mn0; m1 = mn1;
#pragma unroll
        for (int t = 0; t < 8; t++) {
            o[t][0] *= a0; o[t][1] *= a0;
            o[t][2] *= a1; o[t][3] *= a1;
        }

        // ---- O += P V : P frags straight from S registers ----
#pragma unroll
        for (int j = 0; j < 4; j++) {
            uint32_t ph0 = pack_bf16x2(s[2*j][0],   s[2*j][1]);
            uint32_t ph1 = pack_bf16x2(s[2*j][2],   s[2*j][3]);
            uint32_t ph2 = pack_bf16x2(s[2*j+1][0], s[2*j+1][1]);
            uint32_t ph3 = pack_bf16x2(s[2*j+1][2], s[2*j+1][3]);
            uint32_t pl0 = pack_bf16x2(s[2*j][0]   - __uint_as_float(ph0 << 16),
                                       s[2*j][1]   - __uint_as_float(ph0 & 0xFFFF0000u));
            uint32_t pl1 = pack_bf16x2(s[2*j][2]   - __uint_as_float(ph1 << 16),
                                       s[2*j][3]   - __uint_as_float(ph1 & 0xFFFF0000u));
            uint32_t pl2 = pack_bf16x2(s[2*j+1][0] - __uint_as_float(ph2 << 16),
                                       s[2*j+1][1] - __uint_as_float(ph2 & 0xFFFF0000u));
            uint32_t pl3 = pack_bf16x2(s[2*j+1][2] - __uint_as_float(ph3 << 16),
                                       s[2*j+1][3] - __uint_as_float(ph3 & 0xFFFF0000u));
#pragma unroll
            for (int t = 0; t < 8; t++) {
                const int vr = (8 * t + g) * ROWW + 8 * j + q;
                uint32_t vh0 = Vhi[vr], vh1 = Vhi[vr + 4];
                uint32_t vl0 = Vlo[vr], vl1 = Vlo[vr + 4];
                mma_bf16(o[t], ph0, ph1, ph2, ph3, vh0, vh1);
                mma_bf16(o[t], ph0, ph1, ph2, ph3, vl0, vl1);
                mma_bf16(o[t], pl0, pl1, pl2, pl3, vh0, vh1);
            }
        }
    }

    // ---- epilogue: normalize, tf32-round, store [B,T,C] ----
    const float inv0 = 1.f / l0, inv1 = 1.f / l1;
    const size_t ob0 = ((size_t)b * SEQ + row0) * EMB + hofs;
#pragma unroll
    for (int t = 0; t < 8; t++) {
        const int col = 8 * t + 2 * q;
        float2 w0, w1;
        w0.x = tf32r(o[t][0] * inv0); w0.y = tf32r(o[t][1] * inv0);
        w1.x = tf32r(o[t][2] * inv1); w1.y = tf32r(o[t][3] * inv1);
        *(float2*)(out + ob0 + col)            = w0;
        *(float2*)(out + ob0 + 8 * EMB + col)  = w1;
    }
}

// ---------------- launcher ----------------
extern "C" void kernel_launch(void* const* d_in, const int* in_sizes, int n_in,
                              void* d_out, int out_size)
{
    const float* x     = (const float*)d_in[0];
    const float* Wqkv  = (const float*)d_in[1];
    const float* bqkv  = (const float*)d_in[2];
    const float* Wproj = (const float*)d_in[3];
    const float* bproj = (const float*)d_in[4];
    float* out = (float*)d_out;

    float *qkv_p, *att_p, *xr_p, *wq_p, *wp_p;
    cudaGetSymbolAddress((void**)&qkv_p, g_qkv);
    cudaGetSymbolAddress((void**)&att_p, g_att);
    cudaGetSymbolAddress((void**)&xr_p,  g_xr);
    cudaGetSymbolAddress((void**)&wq_p,  g_Wqkv_r);
    cudaGetSymbolAddress((void**)&wp_p,  g_Wproj_r);

    cudaFuncSetAttribute(attn_mma_kernel, cudaFuncAttributeMaxDynamicSharedMemorySize,
                         (int)ATT_SMEM_BYTES);

    // 0) tf32-round inputs/weights for the linear GEMMs
    round_tf32_kernel<<<(M_TOT * EMB / 4 + 255) / 256, 256>>>(x, xr_p, M_TOT * EMB / 4);
    round_tf32_kernel<<<(EMB * C3 / 4 + 255) / 256, 256>>>(Wqkv, wq_p, EMB * C3 / 4);
    round_tf32_kernel<<<(EMB * EMB / 4 + 255) / 256, 256>>>(Wproj, wp_p, EMB * EMB / 4);

    // 1) qkv = x @ W_qkv + b_qkv   (tf32 mma.sync)
    gemm_tf32_mma<<<dim3(C3 / BN, M_TOT / BM), 256>>>(xr_p, wq_p, bqkv, qkv_p, C3);

    // 2) causal attention (bf16x3 mma.sync flash attention)
    attn_mma_kernel<<<dim3(SEQ / 128, NHEAD, BATCH), 256, ATT_SMEM_BYTES>>>(qkv_p, att_p);

    // 3) out = att @ W_proj + b_proj  (tf32 mma.sync)
    gemm_tf32_mma<<<dim3(EMB / BN, M_TOT / BM), 256>>>(att_p, wp_p, bproj, out, EMB);
}

// round 5
// speedup vs baseline: 3.0954x; 1.1255x over previous
#include <cuda_runtime.h>
#include <cuda_bf16.h>
#include <math.h>
#include <stdint.h>

// ---------------- problem constants ----------------
#define BATCH  2
#define SEQ    2048
#define EMB    1024
#define NHEAD  16
#define HDIM   64
#define M_TOT  (BATCH * SEQ)       // 4096
#define C3     (3 * EMB)           // 3072
#define KDIM   1024

// ---------------- scratch ----------------
__device__ float g_qkv[M_TOT * C3];     // 48 MB
__device__ float g_att[M_TOT * EMB];    // 16 MB (attention out, fp32)
__device__ float g_Wqkv_r[EMB * C3];    // 12 MB (tf32-rounded weights)
__device__ float g_Wproj_r[EMB * EMB];  //  4 MB

// ================= helpers =================
__device__ __forceinline__ uint32_t smem_u32(const void* p) {
    uint32_t a;
    asm("{ .reg .u64 t; cvta.to.shared.u64 t, %1; cvt.u32.u64 %0, t; }" : "=r"(a) : "l"(p));
    return a;
}
__device__ __forceinline__ float tf32r(float x) {
    uint32_t r;
    asm("cvt.rna.tf32.f32 %0, %1;" : "=r"(r) : "f"(x));
    return __uint_as_float(r);
}
__device__ __forceinline__ uint32_t tf32r_u(float x) {
    uint32_t r;
    asm("cvt.rna.tf32.f32 %0, %1;" : "=r"(r) : "f"(x));
    return r;
}
__device__ __forceinline__ void cpa16(uint32_t saddr, const void* g) {
    asm volatile("cp.async.cg.shared.global [%0], [%1], 16;" :: "r"(saddr), "l"(g));
}
#define CP_COMMIT()  asm volatile("cp.async.commit_group;")
#define CP_WAIT(n)   asm volatile("cp.async.wait_group %0;" :: "n"(n))

__device__ __forceinline__ void mma_tf32(float* d, const uint32_t* a, const uint32_t* b) {
    asm volatile(
        "mma.sync.aligned.m16n8k8.row.col.f32.tf32.tf32.f32 "
        "{%0,%1,%2,%3}, {%4,%5,%6,%7}, {%8,%9}, {%0,%1,%2,%3};"
        : "+f"(d[0]), "+f"(d[1]), "+f"(d[2]), "+f"(d[3])
        : "r"(a[0]), "r"(a[1]), "r"(a[2]), "r"(a[3]), "r"(b[0]), "r"(b[1]));
}
__device__ __forceinline__ void mma_bf16(float* d, uint32_t a0, uint32_t a1,
                                         uint32_t a2, uint32_t a3,
                                         uint32_t b0, uint32_t b1) {
    asm volatile(
        "mma.sync.aligned.m16n8k16.row.col.f32.bf16.bf16.f32 "
        "{%0,%1,%2,%3}, {%4,%5,%6,%7}, {%8,%9}, {%0,%1,%2,%3};"
        : "+f"(d[0]), "+f"(d[1]), "+f"(d[2]), "+f"(d[3])
        : "r"(a0), "r"(a1), "r"(a2), "r"(a3), "r"(b0), "r"(b1));
}
__device__ __forceinline__ uint32_t pack_bf16x2(float e, float o) {
    uint32_t r;
    asm("cvt.rn.bf16x2.f32 %0, %1, %2;" : "=r"(r) : "f"(o), "f"(e));
    return r;
}
__device__ __forceinline__ void split_store(uint32_t* hiA, uint32_t* loA, int idx,
                                            float e, float o) {
    uint32_t whi = pack_bf16x2(e, o);
    float he = __uint_as_float(whi << 16);
    float ho = __uint_as_float(whi & 0xFFFF0000u);
    hiA[idx] = whi;
    loA[idx] = pack_bf16x2(e - he, o - ho);
}

// ================= tf32 mma.sync GEMM =================
// C[M,N] = round(A) @ B + bias.  A fp32 row-major (rounded in-fragment),
// B pre-rounded row-major.  CTA tile 128x256, BK=16, 8 warps (2Mx4N), warp 64x64.
#define BM 128
#define BN 256
#define BK 16
#define NIT (KDIM / BK)          // 64
#define A_PAD 20                 // bank = 4g+q      (conflict-free)
#define B_PAD 264                // 264%32=8 -> 8q+g (conflict-free)
#define A_STAGE (BM * A_PAD)     // 2560 floats
#define B_STAGE (BK * B_PAD)     // 4224 floats
#define GEMM_SMEM_BYTES (2 * (A_STAGE + B_STAGE) * 4)   // 54272

__global__ void __launch_bounds__(256, 1)
gemm_tf32_mma(const float* __restrict__ A, const float* __restrict__ B,
              const float* __restrict__ bias, float* __restrict__ C, int N)
{
    extern __shared__ float gsm[];
    float* sA = gsm;                       // [2][A_STAGE]
    float* sB = gsm + 2 * A_STAGE;         // [2][B_STAGE]

    const int tid   = threadIdx.x;
    const int wid   = tid >> 5;
    const int lane  = tid & 31;
    const int g     = lane >> 2;
    const int q     = lane & 3;
    const int warpM = wid >> 2;            // 0..1
    const int warpN = wid & 3;             // 0..3
    const int m0    = blockIdx.y * BM;
    const int n0    = blockIdx.x * BN;

    const uint32_t sA0 = smem_u32(sA);
    const uint32_t sB0 = smem_u32(sB);

    auto load_tiles = [&](int it, int s) {
        const int k0 = it * BK;
        const uint32_t aBase = sA0 + s * A_STAGE * 4;
        const uint32_t bBase = sB0 + s * B_STAGE * 4;
#pragma unroll
        for (int j = 0; j < 2; j++) {                 // A: 512 chunks of 16B
            int c = tid + j * 256;
            int r = c >> 2, seg = c & 3;
            cpa16(aBase + (r * A_PAD + seg * 4) * 4,
                  A + (size_t)(m0 + r) * KDIM + k0 + seg * 4);
        }
#pragma unroll
        for (int j = 0; j < 4; j++) {                 // B: 1024 chunks of 16B
            int c = tid + j * 256;
            int r = c >> 6, seg = c & 63;
            cpa16(bBase + (r * B_PAD + seg * 4) * 4,
                  B + (size_t)(k0 + r) * N + n0 + seg * 4);
        }
        CP_COMMIT();
    };

    float acc[4][8][4];
#pragma unroll
    for (int i = 0; i < 4; i++)
#pragma unroll
        for (int j = 0; j < 8; j++)
#pragma unroll
            for (int v = 0; v < 4; v++) acc[i][j][v] = 0.f;

    load_tiles(0, 0);

    const int mbase = warpM * 64;
    const int nbase = warpN * 64;

    for (int it = 0; it < NIT; it++) {
        const int s = it & 1;
        if (it + 1 < NIT) { load_tiles(it + 1, s ^ 1); CP_WAIT(1); }
        else              { CP_WAIT(0); }
        __syncthreads();

        const float* As = sA + s * A_STAGE;
        const float* Bs = sB + s * B_STAGE;

#pragma unroll
        for (int kk = 0; kk < 2; kk++) {
            const int k = kk * 8;
            uint32_t af[4][4], bf[8][2];
#pragma unroll
            for (int mt = 0; mt < 4; mt++) {
                const int rb = mbase + mt * 16;
                af[mt][0] = tf32r_u(As[(rb + g)     * A_PAD + k + q]);
                af[mt][1] = tf32r_u(As[(rb + g + 8) * A_PAD + k + q]);
                af[mt][2] = tf32r_u(As[(rb + g)     * A_PAD + k + q + 4]);
                af[mt][3] = tf32r_u(As[(rb + g + 8) * A_PAD + k + q + 4]);
            }
#pragma unroll
            for (int nt = 0; nt < 8; nt++) {
                const int cb = nbase + nt * 8;
                bf[nt][0] = __float_as_uint(Bs[(k + q)     * B_PAD + cb + g]);
                bf[nt][1] = __float_as_uint(Bs[(k + q + 4) * B_PAD + cb + g]);
            }
#pragma unroll
            for (int mt = 0; mt < 4; mt++)
#pragma unroll
                for (int nt = 0; nt < 8; nt++)
                    mma_tf32(acc[mt][nt], af[mt], bf[nt]);
        }
        __syncthreads();
    }

#pragma unroll
    for (int mt = 0; mt < 4; mt++) {
        const int rm = m0 + mbase + mt * 16 + g;
#pragma unroll
        for (int nt = 0; nt < 8; nt++) {
            const int cn = n0 + nbase + nt * 8 + 2 * q;
            float2 o0, o1;
            o0.x = acc[mt][nt][0] + bias[cn];
            o0.y = acc[mt][nt][1] + bias[cn + 1];
            o1.x = acc[mt][nt][2] + bias[cn];
            o1.y = acc[mt][nt][3] + bias[cn + 1];
            *(float2*)(C + (size_t)rm * N + cn)       = o0;
            *(float2*)(C + (size_t)(rm + 8) * N + cn) = o1;
        }
    }
}

// ================= rounding helper (weights only) =================
__global__ void round_tf32_kernel(const float* __restrict__ in, float* __restrict__ out, int n4)
{
    int i = blockIdx.x * blockDim.x + threadIdx.x;
    if (i < n4) {
        float4 v = ((const float4*)in)[i];
        v.x = tf32r(v.x); v.y = tf32r(v.y); v.z = tf32r(v.z); v.w = tf32r(v.w);
        ((float4*)out)[i] = v;
    }
}

// ================= tensor-core causal flash attention (bf16x3) =================
#define ROWW 36
#define SM_QHI 0
#define SM_QLO (SM_QHI + 128 * ROWW)
#define SM_KHI (SM_QLO + 128 * ROWW)
#define SM_KLO (SM_KHI + 64 * ROWW)
#define SM_VHI (SM_KLO + 64 * ROWW)
#define SM_VLO (SM_VHI + 64 * ROWW)
#define ATT_SMEM_WORDS (SM_VLO + 64 * ROWW)
#define ATT_SMEM_BYTES (ATT_SMEM_WORDS * 4)

__global__ void __launch_bounds__(256)
attn_mma_kernel(const float* __restrict__ qkv, float* __restrict__ out)
{
    extern __shared__ uint32_t sbuf[];
    uint32_t* Qhi = sbuf + SM_QHI;
    uint32_t* Qlo = sbuf + SM_QLO;
    uint32_t* Khi = sbuf + SM_KHI;
    uint32_t* Klo = sbuf + SM_KLO;
    uint32_t* Vhi = sbuf + SM_VHI;
    uint32_t* Vlo = sbuf + SM_VLO;

    const int qt   = (SEQ / 128 - 1) - blockIdx.x;   // heavy tiles first
    const int h    = blockIdx.y;
    const int b    = blockIdx.z;
    const int tid  = threadIdx.x;
    const int w    = tid >> 5;
    const int lane = tid & 31;
    const int g    = lane >> 2;
    const int q    = lane & 3;

    const int hofs = h * HDIM;
    const float* base = qkv + (size_t)b * SEQ * C3;

    for (int i = tid; i < 128 * 32; i += 256) {
        int r = i >> 5, wd = i & 31;
        float2 v = *(const float2*)(base + (size_t)(qt * 128 + r) * C3 + hofs + 2 * wd);
        split_store(Qhi, Qlo, r * ROWW + wd, v.x * 0.125f, v.y * 0.125f);
    }

    float o[8][4];
#pragma unroll
    for (int t = 0; t < 8; t++)
#pragma unroll
        for (int v = 0; v < 4; v++) o[t][v] = 0.f;
    float m0 = -1e30f, m1 = -1e30f, l0 = 0.f, l1 = 0.f;

    const int rb   = w * 16;
    const int row0 = qt * 128 + rb + g;
    const int row1 = row0 + 8;
    const int kend = 2 * qt + 2;

    for (int kt = 0; kt < kend; kt++) {
        __syncthreads();
        for (int i = tid; i < 64 * 32; i += 256) {
            int r = i >> 5, wd = i & 31;
            float2 v = *(const float2*)(base + (size_t)(kt * 64 + r) * C3 + EMB + hofs + 2 * wd);
            split_store(Khi, Klo, r * ROWW + wd, v.x, v.y);
        }
        for (int i = tid; i < 64 * 32; i += 256) {
            int d = i & 63, cw = i >> 6;
            const float* vp = base + (size_t)(kt * 64 + 2 * cw) * C3 + 2 * EMB + hofs + d;
            split_store(Vhi, Vlo, d * ROWW + cw, vp[0], vp[C3]);
        }
        __syncthreads();

        if (kt * 64 > qt * 128 + rb + 15) continue;

        float s[8][4];
#pragma unroll
        for (int t = 0; t < 8; t++)
#pragma unroll
            for (int v = 0; v < 4; v++) s[t][v] = 0.f;

#pragma unroll
        for (int j = 0; j < 4; j++) {
            const int q0 = (rb + g) * ROWW + 8 * j + q;
            const int q1 = (rb + g + 8) * ROWW + 8 * j + q;
            uint32_t qh0 = Qhi[q0], qh1 = Qhi[q1], qh2 = Qhi[q0 + 4], qh3 = Qhi[q1 + 4];
            uint32_t ql0 = Qlo[q0], ql1 = Qlo[q1], ql2 = Qlo[q0 + 4], ql3 = Qlo[q1 + 4];
#pragma unroll
            for (int t = 0; t < 8; t++) {
                const int kr = (8 * t + g) * ROWW + 8 * j + q;
                uint32_t kh0 = Khi[kr], kh1 = Khi[kr + 4];
                uint32_t kl0 = Klo[kr], kl1 = Klo[kr + 4];
                mma_bf16(s[t], qh0, qh1, qh2, qh3, kh0, kh1);
                mma_bf16(s[t], qh0, qh1, qh2, qh3, kl0, kl1);
                mma_bf16(s[t], ql0, ql1, ql2, ql3, kh0, kh1);
            }
        }

        if (kt >= 2 * qt) {
#pragma unroll
            for (int t = 0; t < 8; t++) {
                int col = kt * 64 + 8 * t + 2 * q;
                if (col     > row0) s[t][0] = -1e30f;
                if (col + 1 > row0) s[t][1] = -1e30f;
                if (col     > row1) s[t][2] = -1e30f;
                if (col + 1 > row1) s[t][3] = -1e30f;
            }
        }

        float mx0 = -1e30f, mx1 = -1e30f;
#pragma unroll
        for (int t = 0; t < 8; t++) {
            mx0 = fmaxf(mx0, fmaxf(s[t][0], s[t][1]));
            mx1 = fmaxf(mx1, fmaxf(s[t][2], s[t][3]));
        }
        mx0 = fmaxf(mx0, __shfl_xor_sync(0xffffffffu, mx0, 1));
        mx0 = fmaxf(mx0, __shfl_xor_sync(0xffffffffu, mx0, 2));
        mx1 = fmaxf(mx1, __shfl_xor_sync(0xffffffffu, mx1, 1));
        mx1 = fmaxf(mx1, __shfl_xor_sync(0xffffffffu, mx1, 2));

        float mn0 = fmaxf(m0, mx0), mn1 = fmaxf(m1, mx1);
        float a0 = __expf(m0 - mn0), a1 = __expf(m1 - mn1);
        float sum0 = 0.f, sum1 = 0.f;
#pragma unroll
        for (int t = 0; t < 8; t++) {
            s[t][0] = __expf(s[t][0] - mn0);
            s[t][1] = __expf(s[t][1] - mn0);
            s[t][2] = __expf(s[t][2] - mn1);
            s[t][3] = __expf(s[t][3] - mn1);
            sum0 += s[t][0] + s[t][1];
            sum1 += s[t][2] + s[t][3];
        }
        sum0 += __shfl_xor_sync(0xffffffffu, sum0, 1);
        sum0 += __shfl_xor_sync(0xffffffffu, sum0, 2);
        sum1 += __shfl_xor_sync(0xffffffffu, sum1, 1);
        sum1 += __shfl_xor_sync(0xffffffffu, sum1, 2);
        l0 = l0 * a0 + sum0;
        l1 = l1 * a1 + sum1;
        m0 = mn0; m1 = mn1;
#pragma unroll
        for (int t = 0; t < 8; t++) {
            o[t][0] *= a0; o[t][1] *= a0;
            o[t][2] *= a1; o[t][3] *= a1;
        }

#pragma unroll
        for (int j = 0; j < 4; j++) {
            uint32_t ph0 = pack_bf16x2(s[2*j][0],   s[2*j][1]);
            uint32_t ph1 = pack_bf16x2(s[2*j][2],   s[2*j][3]);
            uint32_t ph2 = pack_bf16x2(s[2*j+1][0], s[2*j+1][1]);
            uint32_t ph3 = pack_bf16x2(s[2*j+1][2], s[2*j+1][3]);
            uint32_t pl0 = pack_bf16x2(s[2*j][0]   - __uint_as_float(ph0 << 16),
                                       s[2*j][1]   - __uint_as_float(ph0 & 0xFFFF0000u));
            uint32_t pl1 = pack_bf16x2(s[2*j][2]   - __uint_as_float(ph1 << 16),
                                       s[2*j][3]   - __uint_as_float(ph1 & 0xFFFF0000u));
            uint32_t pl2 = pack_bf16x2(s[2*j+1][0] - __uint_as_float(ph2 << 16),
                                       s[2*j+1][1] - __uint_as_float(ph2 & 0xFFFF0000u));
            uint32_t pl3 = pack_bf16x2(s[2*j+1][2] - __uint_as_float(ph3 << 16),
                                       s[2*j+1][3] - __uint_as_float(ph3 & 0xFFFF0000u));
#pragma unroll
            for (int t = 0; t < 8; t++) {
                const int vr = (8 * t + g) * ROWW + 8 * j + q;
                uint32_t vh0 = Vhi[vr], vh1 = Vhi[vr + 4];
                uint32_t vl0 = Vlo[vr], vl1 = Vlo[vr + 4];
                mma_bf16(o[t], ph0, ph1, ph2, ph3, vh0, vh1);
                mma_bf16(o[t], ph0, ph1, ph2, ph3, vl0, vl1);
                mma_bf16(o[t], pl0, pl1, pl2, pl3, vh0, vh1);
            }
        }
    }

    const float inv0 = 1.f / l0, inv1 = 1.f / l1;
    const size_t ob0 = ((size_t)b * SEQ + row0) * EMB + hofs;
#pragma unroll
    for (int t = 0; t < 8; t++) {
        const int col = 8 * t + 2 * q;
        float2 w0, w1;
        w0.x = o[t][0] * inv0; w0.y = o[t][1] * inv0;
        w1.x = o[t][2] * inv1; w1.y = o[t][3] * inv1;
        *(float2*)(out + ob0 + col)            = w0;
        *(float2*)(out + ob0 + 8 * EMB + col)  = w1;
    }
}

// ---------------- launcher ----------------
extern "C" void kernel_launch(void* const* d_in, const int* in_sizes, int n_in,
                              void* d_out, int out_size)
{
    const float* x     = (const float*)d_in[0];
    const float* Wqkv  = (const float*)d_in[1];
    const float* bqkv  = (const float*)d_in[2];
    const float* Wproj = (const float*)d_in[3];
    const float* bproj = (const float*)d_in[4];
    float* out = (float*)d_out;

    float *qkv_p, *att_p, *wq_p, *wp_p;
    cudaGetSymbolAddress((void**)&qkv_p, g_qkv);
    cudaGetSymbolAddress((void**)&att_p, g_att);
    cudaGetSymbolAddress((void**)&wq_p,  g_Wqkv_r);
    cudaGetSymbolAddress((void**)&wp_p,  g_Wproj_r);

    cudaFuncSetAttribute(attn_mma_kernel, cudaFuncAttributeMaxDynamicSharedMemorySize,
                         (int)ATT_SMEM_BYTES);
    cudaFuncSetAttribute(gemm_tf32_mma, cudaFuncAttributeMaxDynamicSharedMemorySize,
                         (int)GEMM_SMEM_BYTES);

    // 0) tf32-round weights (reused across 32 row-tiles -> pre-round once)
    round_tf32_kernel<<<(EMB * C3 / 4 + 255) / 256, 256>>>(Wqkv, wq_p, EMB * C3 / 4);
    round_tf32_kernel<<<(EMB * EMB / 4 + 255) / 256, 256>>>(Wproj, wp_p, EMB * EMB / 4);

    // 1) qkv = x @ W_qkv + b_qkv   (tf32 mma.sync; A rounded in-fragment)
    gemm_tf32_mma<<<dim3(C3 / BN, M_TOT / BM), 256, GEMM_SMEM_BYTES>>>(x, wq_p, bqkv, qkv_p, C3);

    // 2) causal attention (bf16x3 mma.sync flash attention)
    attn_mma_kernel<<<dim3(SEQ / 128, NHEAD, BATCH), 256, ATT_SMEM_BYTES>>>(qkv_p, att_p);

    // 3) out = att @ W_proj + b_proj
    gemm_tf32_mma<<<dim3(EMB / BN, M_TOT / BM), 256, GEMM_SMEM_BYTES>>>(att_p, wp_p, bproj, out, EMB);
}

// round 6
// speedup vs baseline: 3.1725x; 1.0249x over previous
#include <cuda_runtime.h>
#include <cuda_bf16.h>
#include <math.h>
#include <stdint.h>

// ---------------- problem constants ----------------
#define BATCH  2
#define SEQ    2048
#define EMB    1024
#define NHEAD  16
#define HDIM   64
#define M_TOT  (BATCH * SEQ)       // 4096
#define C3     (3 * EMB)           // 3072
#define KDIM   1024

// ---------------- scratch ----------------
__device__ float    g_qkv[M_TOT * C3];        // 48 MB
__device__ float    g_att[M_TOT * EMB];       // 16 MB
__device__ float    g_Wqkv_r[EMB * C3];       // 12 MB
__device__ float    g_Wproj_r[EMB * EMB];     //  4 MB
// pre-split bf16 planes (stored as packed bf16x2 words)
__device__ uint32_t g_qhi[M_TOT * EMB / 2];   // Q*0.125 hi
__device__ uint32_t g_qlo[M_TOT * EMB / 2];
__device__ uint32_t g_khi[M_TOT * EMB / 2];
__device__ uint32_t g_klo[M_TOT * EMB / 2];
__device__ uint32_t g_vthi[M_TOT * EMB / 2];  // V^T per head: [b][h][d][seq]
__device__ uint32_t g_vtlo[M_TOT * EMB / 2];

// ================= helpers =================
__device__ __forceinline__ uint32_t smem_u32(const void* p) {
    uint32_t a;
    asm("{ .reg .u64 t; cvta.to.shared.u64 t, %1; cvt.u32.u64 %0, t; }" : "=r"(a) : "l"(p));
    return a;
}
__device__ __forceinline__ float tf32r(float x) {
    uint32_t r;
    asm("cvt.rna.tf32.f32 %0, %1;" : "=r"(r) : "f"(x));
    return __uint_as_float(r);
}
__device__ __forceinline__ uint32_t tf32r_u(float x) {
    uint32_t r;
    asm("cvt.rna.tf32.f32 %0, %1;" : "=r"(r) : "f"(x));
    return r;
}
__device__ __forceinline__ void cpa16(uint32_t saddr, const void* g) {
    asm volatile("cp.async.cg.shared.global [%0], [%1], 16;" :: "r"(saddr), "l"(g));
}
#define CP_COMMIT()  asm volatile("cp.async.commit_group;")
#define CP_WAIT(n)   asm volatile("cp.async.wait_group %0;" :: "n"(n))

__device__ __forceinline__ void mma_tf32(float* d, const uint32_t* a, const uint32_t* b) {
    asm volatile(
        "mma.sync.aligned.m16n8k8.row.col.f32.tf32.tf32.f32 "
        "{%0,%1,%2,%3}, {%4,%5,%6,%7}, {%8,%9}, {%0,%1,%2,%3};"
        : "+f"(d[0]), "+f"(d[1]), "+f"(d[2]), "+f"(d[3])
        : "r"(a[0]), "r"(a[1]), "r"(a[2]), "r"(a[3]), "r"(b[0]), "r"(b[1]));
}
__device__ __forceinline__ void mma_bf16(float* d, uint32_t a0, uint32_t a1,
                                         uint32_t a2, uint32_t a3,
                                         uint32_t b0, uint32_t b1) {
    asm volatile(
        "mma.sync.aligned.m16n8k16.row.col.f32.bf16.bf16.f32 "
        "{%0,%1,%2,%3}, {%4,%5,%6,%7}, {%8,%9}, {%0,%1,%2,%3};"
        : "+f"(d[0]), "+f"(d[1]), "+f"(d[2]), "+f"(d[3])
        : "r"(a0), "r"(a1), "r"(a2), "r"(a3), "r"(b0), "r"(b1));
}
__device__ __forceinline__ uint32_t pack_bf16x2(float e, float o) {
    uint32_t r;
    asm("cvt.rn.bf16x2.f32 %0, %1, %2;" : "=r"(r) : "f"(o), "f"(e));
    return r;
}
// split pair -> (hi word, lo word)
__device__ __forceinline__ void split2(float e, float o, uint32_t& whi, uint32_t& wlo) {
    whi = pack_bf16x2(e, o);
    float he = __uint_as_float(whi << 16);
    float ho = __uint_as_float(whi & 0xFFFF0000u);
    wlo = pack_bf16x2(e - he, o - ho);
}

// ================= tf32 mma.sync GEMM (round-5 proven) =================
#define BM 128
#define BN 256
#define BK 16
#define NIT (KDIM / BK)
#define A_PAD 20
#define B_PAD 264
#define A_STAGE (BM * A_PAD)
#define B_STAGE (BK * B_PAD)
#define GEMM_SMEM_BYTES (2 * (A_STAGE + B_STAGE) * 4)

__global__ void __launch_bounds__(256, 1)
gemm_tf32_mma(const float* __restrict__ A, const float* __restrict__ B,
              const float* __restrict__ bias, float* __restrict__ C, int N)
{
    extern __shared__ float gsm[];
    float* sA = gsm;
    float* sB = gsm + 2 * A_STAGE;

    const int tid   = threadIdx.x;
    const int wid   = tid >> 5;
    const int lane  = tid & 31;
    const int g     = lane >> 2;
    const int q     = lane & 3;
    const int warpM = wid >> 2;
    const int warpN = wid & 3;
    const int m0    = blockIdx.y * BM;
    const int n0    = blockIdx.x * BN;

    const uint32_t sA0 = smem_u32(sA);
    const uint32_t sB0 = smem_u32(sB);

    auto load_tiles = [&](int it, int s) {
        const int k0 = it * BK;
        const uint32_t aBase = sA0 + s * A_STAGE * 4;
        const uint32_t bBase = sB0 + s * B_STAGE * 4;
#pragma unroll
        for (int j = 0; j < 2; j++) {
            int c = tid + j * 256;
            int r = c >> 2, seg = c & 3;
            cpa16(aBase + (r * A_PAD + seg * 4) * 4,
                  A + (size_t)(m0 + r) * KDIM + k0 + seg * 4);
        }
#pragma unroll
        for (int j = 0; j < 4; j++) {
            int c = tid + j * 256;
            int r = c >> 6, seg = c & 63;
            cpa16(bBase + (r * B_PAD + seg * 4) * 4,
                  B + (size_t)(k0 + r) * N + n0 + seg * 4);
        }
        CP_COMMIT();
    };

    float acc[4][8][4];
#pragma unroll
    for (int i = 0; i < 4; i++)
#pragma unroll
        for (int j = 0; j < 8; j++)
#pragma unroll
            for (int v = 0; v < 4; v++) acc[i][j][v] = 0.f;

    load_tiles(0, 0);

    const int mbase = warpM * 64;
    const int nbase = warpN * 64;

    for (int it = 0; it < NIT; it++) {
        const int s = it & 1;
        if (it + 1 < NIT) { load_tiles(it + 1, s ^ 1); CP_WAIT(1); }
        else              { CP_WAIT(0); }
        __syncthreads();

        const float* As = sA + s * A_STAGE;
        const float* Bs = sB + s * B_STAGE;

#pragma unroll
        for (int kk = 0; kk < 2; kk++) {
            const int k = kk * 8;
            uint32_t af[4][4], bf[8][2];
#pragma unroll
            for (int mt = 0; mt < 4; mt++) {
                const int rb = mbase + mt * 16;
                af[mt][0] = tf32r_u(As[(rb + g)     * A_PAD + k + q]);
                af[mt][1] = tf32r_u(As[(rb + g + 8) * A_PAD + k + q]);
                af[mt][2] = tf32r_u(As[(rb + g)     * A_PAD + k + q + 4]);
                af[mt][3] = tf32r_u(As[(rb + g + 8) * A_PAD + k + q + 4]);
            }
#pragma unroll
            for (int nt = 0; nt < 8; nt++) {
                const int cb = nbase + nt * 8;
                bf[nt][0] = __float_as_uint(Bs[(k + q)     * B_PAD + cb + g]);
                bf[nt][1] = __float_as_uint(Bs[(k + q + 4) * B_PAD + cb + g]);
            }
#pragma unroll
            for (int mt = 0; mt < 4; mt++)
#pragma unroll
                for (int nt = 0; nt < 8; nt++)
                    mma_tf32(acc[mt][nt], af[mt], bf[nt]);
        }
        __syncthreads();
    }

#pragma unroll
    for (int mt = 0; mt < 4; mt++) {
        const int rm = m0 + mbase + mt * 16 + g;
#pragma unroll
        for (int nt = 0; nt < 8; nt++) {
            const int cn = n0 + nbase + nt * 8 + 2 * q;
            float2 o0, o1;
            o0.x = acc[mt][nt][0] + bias[cn];
            o0.y = acc[mt][nt][1] + bias[cn + 1];
            o1.x = acc[mt][nt][2] + bias[cn];
            o1.y = acc[mt][nt][3] + bias[cn + 1];
            *(float2*)(C + (size_t)rm * N + cn)       = o0;
            *(float2*)(C + (size_t)(rm + 8) * N + cn) = o1;
        }
    }
}

// ================= rounding helper (weights) =================
__global__ void round_tf32_kernel(const float* __restrict__ in, float* __restrict__ out, int n4)
{
    int i = blockIdx.x * blockDim.x + threadIdx.x;
    if (i < n4) {
        float4 v = ((const float4*)in)[i];
        v.x = tf32r(v.x); v.y = tf32r(v.y); v.z = tf32r(v.z); v.w = tf32r(v.w);
        ((float4*)out)[i] = v;
    }
}

// ================= prepass 1: split Q (scaled) and K =================
// one thread per float4 (4 elems) of the per-token 1024-dim vector
__global__ void __launch_bounds__(256)
split_qk_kernel(const float* __restrict__ qkv,
                uint32_t* __restrict__ qhi, uint32_t* __restrict__ qlo,
                uint32_t* __restrict__ khi, uint32_t* __restrict__ klo)
{
    int i = blockIdx.x * blockDim.x + threadIdx.x;   // 0 .. M_TOT*EMB/4-1
    if (i >= M_TOT * EMB / 4) return;
    int bt = i >> 8;            // token
    int c4 = i & 255;           // float4 within 1024 dims
    const float* p = qkv + (size_t)bt * C3 + c4 * 4;
    float4 qv = *(const float4*)p;
    float4 kv = *(const float4*)(p + EMB);
    uint32_t h0, l0, h1, l1;
    int w = bt * (EMB / 2) + c4 * 2;
    split2(qv.x * 0.125f, qv.y * 0.125f, h0, l0);
    split2(qv.z * 0.125f, qv.w * 0.125f, h1, l1);
    qhi[w] = h0; qhi[w + 1] = h1; qlo[w] = l0; qlo[w + 1] = l1;
    split2(kv.x, kv.y, h0, l0);
    split2(kv.z, kv.w, h1, l1);
    khi[w] = h0; khi[w + 1] = h1; klo[w] = l0; klo[w + 1] = l1;
}

// ================= prepass 2: transpose+split V per head =================
// grid (SEQ/64, NHEAD, BATCH), block 256. Vt[b][h][d][seq] bf16 pairs along seq.
__global__ void __launch_bounds__(256)
transpose_v_kernel(const float* __restrict__ qkv,
                   uint32_t* __restrict__ vthi, uint32_t* __restrict__ vtlo)
{
    __shared__ float tile[64][65];
    const int s0 = blockIdx.x * 64;
    const int h  = blockIdx.y;
    const int b  = blockIdx.z;
    const int tid = threadIdx.x;

#pragma unroll
    for (int j = 0; j < 16; j++) {
        int idx = tid + j * 256;
        int r = idx >> 6, d = idx & 63;
        tile[r][d] = qkv[(size_t)(b * SEQ + s0 + r) * C3 + 2 * EMB + h * HDIM + d];
    }
    __syncthreads();

    const int wv = tid & 31;        // word (key-pair) within row
    const int dq = tid >> 5;        // 0..7
#pragma unroll
    for (int j = 0; j < 8; j++) {
        int d = dq * 8 + j;
        float e = tile[2 * wv][d];
        float o = tile[2 * wv + 1][d];
        uint32_t whi, wlo;
        split2(e, o, whi, wlo);
        size_t wi = ((size_t)(b * NHEAD + h) * HDIM + d) * (SEQ / 2) + s0 / 2 + wv;
        vthi[wi] = whi;
        vtlo[wi] = wlo;
    }
}

// ================= tensor-core causal flash attention (bf16x3, cp.async) =================
#define ROWW 36
#define Q_WORDS      (128 * ROWW)                 // per array
#define KV_ARR_WORDS (64 * ROWW)                  // 2304
#define STAGE_WORDS  (4 * KV_ARR_WORDS)           // 9216
#define ATT_SMEM_WORDS (2 * Q_WORDS + 2 * STAGE_WORDS)
#define ATT_SMEM_BYTES (ATT_SMEM_WORDS * 4)       // 110592

__global__ void __launch_bounds__(256)
attn_mma_kernel(const uint32_t* __restrict__ qhi, const uint32_t* __restrict__ qlo,
                const uint32_t* __restrict__ khi, const uint32_t* __restrict__ klo,
                const uint32_t* __restrict__ vthi, const uint32_t* __restrict__ vtlo,
                float* __restrict__ out)
{
    extern __shared__ uint32_t sbuf[];
    uint32_t* Qhi = sbuf;
    uint32_t* Qlo = Qhi + Q_WORDS;
    uint32_t* KV  = Qlo + Q_WORDS;

    const int qt   = (SEQ / 128 - 1) - blockIdx.x;
    const int h    = blockIdx.y;
    const int b    = blockIdx.z;
    const int tid  = threadIdx.x;
    const int w    = tid >> 5;
    const int lane = tid & 31;
    const int g    = lane >> 2;
    const int q    = lane & 3;

    const uint32_t kvS = smem_u32(KV);

    // byte bases into global planes
    const char* qhiB = (const char*)qhi;
    const char* qloB = (const char*)qlo;
    const char* khiB = (const char*)khi;
    const char* kloB = (const char*)klo;
    const char* vhiB = (const char*)vthi;
    const char* vloB = (const char*)vtlo;
    const size_t qkRow0 = ((size_t)(b * SEQ) * EMB + h * HDIM) * 2;      // token row 0, bytes
    const size_t vRow0  = ((size_t)(b * NHEAD + h) * HDIM) * SEQ * 2;    // d row 0, bytes

    // ---- prologue: Q (both planes) + stage 0 K/V ----
    {
        const uint32_t qs_hi = smem_u32(Qhi);
        const uint32_t qs_lo = smem_u32(Qlo);
#pragma unroll
        for (int j = 0; j < 8; j++) {
            int rem = ((j & 3) << 8) | tid;       // 0..1023
            int row = rem >> 3, ch = rem & 7;
            uint32_t sa = (j < 4 ? qs_hi : qs_lo) + row * 144 + ch * 16;
            const char* gp = (j < 4 ? qhiB : qloB) +
                             qkRow0 + (size_t)(qt * 128 + row) * (EMB * 2) + ch * 16;
            cpa16(sa, gp);
        }
    }
    auto load_kv = [&](int kt, int s) {
        const uint32_t st = kvS + s * STAGE_WORDS * 4;
#pragma unroll
        for (int j = 0; j < 8; j++) {
            int arr = j >> 1;                      // 0:Khi 1:Klo 2:Vhi 3:Vlo
            int rem = ((j & 1) << 8) | tid;        // 0..511
            int row = rem >> 3, ch = rem & 7;
            uint32_t sa = st + arr * (KV_ARR_WORDS * 4) + row * 144 + ch * 16;
            const char* gp;
            if (arr == 0)
                gp = khiB + qkRow0 + (size_t)(kt * 64 + row) * (EMB * 2) + ch * 16;
            else if (arr == 1)
                gp = kloB + qkRow0 + (size_t)(kt * 64 + row) * (EMB * 2) + ch * 16;
            else if (arr == 2)
                gp = vhiB + vRow0 + (size_t)row * (SEQ * 2) + kt * 128 + ch * 16;
            else
                gp = vloB + vRow0 + (size_t)row * (SEQ * 2) + kt * 128 + ch * 16;
            cpa16(sa, gp);
        }
    };
    load_kv(0, 0);
    CP_COMMIT();

    float o[8][4];
#pragma unroll
    for (int t = 0; t < 8; t++)
#pragma unroll
        for (int v = 0; v < 4; v++) o[t][v] = 0.f;
    float m0 = -1e30f, m1 = -1e30f, l0 = 0.f, l1 = 0.f;

    const int rb   = w * 16;
    const int row0 = qt * 128 + rb + g;
    const int row1 = row0 + 8;
    const int kend = 2 * qt + 2;

    for (int kt = 0; kt < kend; kt++) {
        const int s = kt & 1;
        CP_WAIT(0);
        __syncthreads();
        if (kt + 1 < kend) { load_kv(kt + 1, s ^ 1); CP_COMMIT(); }

        if (kt * 64 <= qt * 128 + rb + 15) {
            uint32_t* Khi = KV + s * STAGE_WORDS;
            uint32_t* Klo = Khi + KV_ARR_WORDS;
            uint32_t* Vhi = Klo + KV_ARR_WORDS;
            uint32_t* Vlo = Vhi + KV_ARR_WORDS;

            float sc[8][4];
#pragma unroll
            for (int t = 0; t < 8; t++)
#pragma unroll
                for (int v = 0; v < 4; v++) sc[t][v] = 0.f;

#pragma unroll
            for (int j = 0; j < 4; j++) {
                const int q0 = (rb + g) * ROWW + 8 * j + q;
                const int q1 = (rb + g + 8) * ROWW + 8 * j + q;
                uint32_t qh0 = Qhi[q0], qh1 = Qhi[q1], qh2 = Qhi[q0 + 4], qh3 = Qhi[q1 + 4];
                uint32_t ql0 = Qlo[q0], ql1 = Qlo[q1], ql2 = Qlo[q0 + 4], ql3 = Qlo[q1 + 4];
#pragma unroll
                for (int t = 0; t < 8; t++) {
                    const int kr = (8 * t + g) * ROWW + 8 * j + q;
                    uint32_t kh0 = Khi[kr], kh1 = Khi[kr + 4];
                    uint32_t kl0 = Klo[kr], kl1 = Klo[kr + 4];
                    mma_bf16(sc[t], qh0, qh1, qh2, qh3, kh0, kh1);
                    mma_bf16(sc[t], qh0, qh1, qh2, qh3, kl0, kl1);
                    mma_bf16(sc[t], ql0, ql1, ql2, ql3, kh0, kh1);
                }
            }

            if (kt >= 2 * qt) {
#pragma unroll
                for (int t = 0; t < 8; t++) {
                    int col = kt * 64 + 8 * t + 2 * q;
                    if (col     > row0) sc[t][0] = -1e30f;
                    if (col + 1 > row0) sc[t][1] = -1e30f;
                    if (col     > row1) sc[t][2] = -1e30f;
                    if (col + 1 > row1) sc[t][3] = -1e30f;
                }
            }

            float mx0 = -1e30f, mx1 = -1e30f;
#pragma unroll
            for (int t = 0; t < 8; t++) {
                mx0 = fmaxf(mx0, fmaxf(sc[t][0], sc[t][1]));
                mx1 = fmaxf(mx1, fmaxf(sc[t][2], sc[t][3]));
            }
            mx0 = fmaxf(mx0, __shfl_xor_sync(0xffffffffu, mx0, 1));
            mx0 = fmaxf(mx0, __shfl_xor_sync(0xffffffffu, mx0, 2));
            mx1 = fmaxf(mx1, __shfl_xor_sync(0xffffffffu, mx1, 1));
            mx1 = fmaxf(mx1, __shfl_xor_sync(0xffffffffu, mx1, 2));

            float mn0 = fmaxf(m0, mx0), mn1 = fmaxf(m1, mx1);
            float a0 = __expf(m0 - mn0), a1 = __expf(m1 - mn1);
            float sum0 = 0.f, sum1 = 0.f;
#pragma unroll
            for (int t = 0; t < 8; t++) {
                sc[t][0] = __expf(sc[t][0] - mn0);
                sc[t][1] = __expf(sc[t][1] - mn0);
                sc[t][2] = __expf(sc[t][2] - mn1);
                sc[t][3] = __expf(sc[t][3] - mn1);
                sum0 += sc[t][0] + sc[t][1];
                sum1 += sc[t][2] + sc[t][3];
            }
            sum0 += __shfl_xor_sync(0xffffffffu, sum0, 1);
            sum0 += __shfl_xor_sync(0xffffffffu, sum0, 2);
            sum1 += __shfl_xor_sync(0xffffffffu, sum1, 1);
            sum1 += __shfl_xor_sync(0xffffffffu, sum1, 2);
            l0 = l0 * a0 + sum0;
            l1 = l1 * a1 + sum1;
            m0 = mn0; m1 = mn1;
#pragma unroll
            for (int t = 0; t < 8; t++) {
                o[t][0] *= a0; o[t][1] *= a0;
                o[t][2] *= a1; o[t][3] *= a1;
            }

#pragma unroll
            for (int j = 0; j < 4; j++) {
                uint32_t ph0 = pack_bf16x2(sc[2*j][0],   sc[2*j][1]);
                uint32_t ph1 = pack_bf16x2(sc[2*j][2],   sc[2*j][3]);
                uint32_t ph2 = pack_bf16x2(sc[2*j+1][0], sc[2*j+1][1]);
                uint32_t ph3 = pack_bf16x2(sc[2*j+1][2], sc[2*j+1][3]);
                uint32_t pl0 = pack_bf16x2(sc[2*j][0]   - __uint_as_float(ph0 << 16),
                                           sc[2*j][1]   - __uint_as_float(ph0 & 0xFFFF0000u));
                uint32_t pl1 = pack_bf16x2(sc[2*j][2]   - __uint_as_float(ph1 << 16),
                                           sc[2*j][3]   - __uint_as_float(ph1 & 0xFFFF0000u));
                uint32_t pl2 = pack_bf16x2(sc[2*j+1][0] - __uint_as_float(ph2 << 16),
                                           sc[2*j+1][1] - __uint_as_float(ph2 & 0xFFFF0000u));
                uint32_t pl3 = pack_bf16x2(sc[2*j+1][2] - __uint_as_float(ph3 << 16),
                                           sc[2*j+1][3] - __uint_as_float(ph3 & 0xFFFF0000u));
#pragma unroll
                for (int t = 0; t < 8; t++) {
                    const int vr = (8 * t + g) * ROWW + 8 * j + q;
                    uint32_t vh0 = Vhi[vr], vh1 = Vhi[vr + 4];
                    uint32_t vl0 = Vlo[vr], vl1 = Vlo[vr + 4];
                    mma_bf16(o[t], ph0, ph1, ph2, ph3, vh0, vh1);
                    mma_bf16(o[t], ph0, ph1, ph2, ph3, vl0, vl1);
                    mma_bf16(o[t], pl0, pl1, pl2, pl3, vh0, vh1);
                }
            }
        }
        __syncthreads();
    }

    const float inv0 = 1.f / l0, inv1 = 1.f / l1;
    const size_t ob0 = ((size_t)b * SEQ + row0) * EMB + h * HDIM;
#pragma unroll
    for (int t = 0; t < 8; t++) {
        const int col = 8 * t + 2 * q;
        float2 w0, w1;
        w0.x = o[t][0] * inv0; w0.y = o[t][1] * inv0;
        w1.x = o[t][2] * inv1; w1.y = o[t][3] * inv1;
        *(float2*)(out + ob0 + col)            = w0;
        *(float2*)(out + ob0 + 8 * EMB + col)  = w1;
    }
}

// ---------------- launcher ----------------
extern "C" void kernel_launch(void* const* d_in, const int* in_sizes, int n_in,
                              void* d_out, int out_size)
{
    const float* x     = (const float*)d_in[0];
    const float* Wqkv  = (const float*)d_in[1];
    const float* bqkv  = (const float*)d_in[2];
    const float* Wproj = (const float*)d_in[3];
    const float* bproj = (const float*)d_in[4];
    float* out = (float*)d_out;

    float *qkv_p, *att_p, *wq_p, *wp_p;
    uint32_t *qhi_p, *qlo_p, *khi_p, *klo_p, *vhi_p, *vlo_p;
    cudaGetSymbolAddress((void**)&qkv_p, g_qkv);
    cudaGetSymbolAddress((void**)&att_p, g_att);
    cudaGetSymbolAddress((void**)&wq_p,  g_Wqkv_r);
    cudaGetSymbolAddress((void**)&wp_p,  g_Wproj_r);
    cudaGetSymbolAddress((void**)&qhi_p, g_qhi);
    cudaGetSymbolAddress((void**)&qlo_p, g_qlo);
    cudaGetSymbolAddress((void**)&khi_p, g_khi);
    cudaGetSymbolAddress((void**)&klo_p, g_klo);
    cudaGetSymbolAddress((void**)&vhi_p, g_vthi);
    cudaGetSymbolAddress((void**)&vlo_p, g_vtlo);

    cudaFuncSetAttribute(attn_mma_kernel, cudaFuncAttributeMaxDynamicSharedMemorySize,
                         (int)ATT_SMEM_BYTES);
    cudaFuncSetAttribute(gemm_tf32_mma, cudaFuncAttributeMaxDynamicSharedMemorySize,
                         (int)GEMM_SMEM_BYTES);

    // 0) tf32-round weights
    round_tf32_kernel<<<(EMB * C3 / 4 + 255) / 256, 256>>>(Wqkv, wq_p, EMB * C3 / 4);
    round_tf32_kernel<<<(EMB * EMB / 4 + 255) / 256, 256>>>(Wproj, wp_p, EMB * EMB / 4);

    // 1) qkv = x @ W_qkv + b_qkv
    gemm_tf32_mma<<<dim3(C3 / BN, M_TOT / BM), 256, GEMM_SMEM_BYTES>>>(x, wq_p, bqkv, qkv_p, C3);

    // 2a) pre-split Q/K, transpose+split V
    split_qk_kernel<<<(M_TOT * EMB / 4 + 255) / 256, 256>>>(qkv_p, qhi_p, qlo_p, khi_p, klo_p);
    transpose_v_kernel<<<dim3(SEQ / 64, NHEAD, BATCH), 256>>>(qkv_p, vhi_p, vlo_p);

    // 2b) causal attention
    attn_mma_kernel<<<dim3(SEQ / 128, NHEAD, BATCH), 256, ATT_SMEM_BYTES>>>(
        qhi_p, qlo_p, khi_p, klo_p, vhi_p, vlo_p, att_p);

    // 3) out = att @ W_proj + b_proj
    gemm_tf32_mma<<<dim3(EMB / BN, M_TOT / BM), 256, GEMM_SMEM_BYTES>>>(att_p, wp_p, bproj, out, EMB);
}

// round 7
// speedup vs baseline: 3.2874x; 1.0362x over previous
#include <cuda_runtime.h>
#include <cuda_bf16.h>
#include <math.h>
#include <stdint.h>

// ---------------- problem constants ----------------
#define BATCH  2
#define SEQ    2048
#define EMB    1024
#define NHEAD  16
#define HDIM   64
#define M_TOT  (BATCH * SEQ)       // 4096
#define C3     (3 * EMB)           // 3072
#define KDIM   1024

// ---------------- scratch ----------------
__device__ float    g_qkv[M_TOT * C3];        // 48 MB
__device__ float    g_att[M_TOT * EMB];       // 16 MB
__device__ float    g_Wqkv_r[EMB * C3];       // 12 MB
__device__ float    g_Wproj_r[EMB * EMB];     //  4 MB
__device__ uint32_t g_qhi[M_TOT * EMB / 2];   // Q*(0.125*log2e) hi
__device__ uint32_t g_qlo[M_TOT * EMB / 2];
__device__ uint32_t g_khi[M_TOT * EMB / 2];
__device__ uint32_t g_klo[M_TOT * EMB / 2];
__device__ uint32_t g_vthi[M_TOT * EMB / 2];  // V^T per head: [b][h][d][seq]
__device__ uint32_t g_vtlo[M_TOT * EMB / 2];

// ================= helpers =================
__device__ __forceinline__ uint32_t smem_u32(const void* p) {
    uint32_t a;
    asm("{ .reg .u64 t; cvta.to.shared.u64 t, %1; cvt.u32.u64 %0, t; }" : "=r"(a) : "l"(p));
    return a;
}
__device__ __forceinline__ float tf32r(float x) {
    uint32_t r;
    asm("cvt.rna.tf32.f32 %0, %1;" : "=r"(r) : "f"(x));
    return __uint_as_float(r);
}
__device__ __forceinline__ uint32_t tf32r_u(float x) {
    uint32_t r;
    asm("cvt.rna.tf32.f32 %0, %1;" : "=r"(r) : "f"(x));
    return r;
}
__device__ __forceinline__ void cpa16(uint32_t saddr, const void* g) {
    asm volatile("cp.async.cg.shared.global [%0], [%1], 16;" :: "r"(saddr), "l"(g));
}
#define CP_COMMIT()  asm volatile("cp.async.commit_group;")
#define CP_WAIT(n)   asm volatile("cp.async.wait_group %0;" :: "n"(n))

__device__ __forceinline__ void mma_tf32(float* d, const uint32_t* a, const uint32_t* b) {
    asm volatile(
        "mma.sync.aligned.m16n8k8.row.col.f32.tf32.tf32.f32 "
        "{%0,%1,%2,%3}, {%4,%5,%6,%7}, {%8,%9}, {%0,%1,%2,%3};"
        : "+f"(d[0]), "+f"(d[1]), "+f"(d[2]), "+f"(d[3])
        : "r"(a[0]), "r"(a[1]), "r"(a[2]), "r"(a[3]), "r"(b[0]), "r"(b[1]));
}
__device__ __forceinline__ void mma_bf16(float* d, uint32_t a0, uint32_t a1,
                                         uint32_t a2, uint32_t a3,
                                         uint32_t b0, uint32_t b1) {
    asm volatile(
        "mma.sync.aligned.m16n8k16.row.col.f32.bf16.bf16.f32 "
        "{%0,%1,%2,%3}, {%4,%5,%6,%7}, {%8,%9}, {%0,%1,%2,%3};"
        : "+f"(d[0]), "+f"(d[1]), "+f"(d[2]), "+f"(d[3])
        : "r"(a0), "r"(a1), "r"(a2), "r"(a3), "r"(b0), "r"(b1));
}
__device__ __forceinline__ void ldsm_x4(uint32_t& r0, uint32_t& r1, uint32_t& r2,
                                        uint32_t& r3, uint32_t addr) {
    asm volatile("ldmatrix.sync.aligned.m8n8.x4.shared.b16 {%0,%1,%2,%3}, [%4];"
                 : "=r"(r0), "=r"(r1), "=r"(r2), "=r"(r3) : "r"(addr));
}
__device__ __forceinline__ uint32_t pack_bf16x2(float e, float o) {
    uint32_t r;
    asm("cvt.rn.bf16x2.f32 %0, %1, %2;" : "=r"(r) : "f"(o), "f"(e));
    return r;
}
__device__ __forceinline__ void split2(float e, float o, uint32_t& whi, uint32_t& wlo) {
    whi = pack_bf16x2(e, o);
    float he = __uint_as_float(whi << 16);
    float ho = __uint_as_float(whi & 0xFFFF0000u);
    wlo = pack_bf16x2(e - he, o - ho);
}

// ================= tf32 mma.sync GEMM (round-5 proven) =================
#define BM 128
#define BN 256
#define BK 16
#define NIT (KDIM / BK)
#define A_PAD 20
#define B_PAD 264
#define A_STAGE (BM * A_PAD)
#define B_STAGE (BK * B_PAD)
#define GEMM_SMEM_BYTES (2 * (A_STAGE + B_STAGE) * 4)

__global__ void __launch_bounds__(256, 1)
gemm_tf32_mma(const float* __restrict__ A, const float* __restrict__ B,
              const float* __restrict__ bias, float* __restrict__ C, int N)
{
    extern __shared__ float gsm[];
    float* sA = gsm;
    float* sB = gsm + 2 * A_STAGE;

    const int tid   = threadIdx.x;
    const int wid   = tid >> 5;
    const int lane  = tid & 31;
    const int g     = lane >> 2;
    const int q     = lane & 3;
    const int warpM = wid >> 2;
    const int warpN = wid & 3;
    const int m0    = blockIdx.y * BM;
    const int n0    = blockIdx.x * BN;

    const uint32_t sA0 = smem_u32(sA);
    const uint32_t sB0 = smem_u32(sB);

    auto load_tiles = [&](int it, int s) {
        const int k0 = it * BK;
        const uint32_t aBase = sA0 + s * A_STAGE * 4;
        const uint32_t bBase = sB0 + s * B_STAGE * 4;
#pragma unroll
        for (int j = 0; j < 2; j++) {
            int c = tid + j * 256;
            int r = c >> 2, seg = c & 3;
            cpa16(aBase + (r * A_PAD + seg * 4) * 4,
                  A + (size_t)(m0 + r) * KDIM + k0 + seg * 4);
        }
#pragma unroll
        for (int j = 0; j < 4; j++) {
            int c = tid + j * 256;
            int r = c >> 6, seg = c & 63;
            cpa16(bBase + (r * B_PAD + seg * 4) * 4,
                  B + (size_t)(k0 + r) * N + n0 + seg * 4);
        }
        CP_COMMIT();
    };

    float acc[4][8][4];
#pragma unroll
    for (int i = 0; i < 4; i++)
#pragma unroll
        for (int j = 0; j < 8; j++)
#pragma unroll
            for (int v = 0; v < 4; v++) acc[i][j][v] = 0.f;

    load_tiles(0, 0);

    const int mbase = warpM * 64;
    const int nbase = warpN * 64;

    for (int it = 0; it < NIT; it++) {
        const int s = it & 1;
        if (it + 1 < NIT) { load_tiles(it + 1, s ^ 1); CP_WAIT(1); }
        else              { CP_WAIT(0); }
        __syncthreads();

        const float* As = sA + s * A_STAGE;
        const float* Bs = sB + s * B_STAGE;

#pragma unroll
        for (int kk = 0; kk < 2; kk++) {
            const int k = kk * 8;
            uint32_t af[4][4], bf[8][2];
#pragma unroll
            for (int mt = 0; mt < 4; mt++) {
                const int rb = mbase + mt * 16;
                af[mt][0] = tf32r_u(As[(rb + g)     * A_PAD + k + q]);
                af[mt][1] = tf32r_u(As[(rb + g + 8) * A_PAD + k + q]);
                af[mt][2] = tf32r_u(As[(rb + g)     * A_PAD + k + q + 4]);
                af[mt][3] = tf32r_u(As[(rb + g + 8) * A_PAD + k + q + 4]);
            }
#pragma unroll
            for (int nt = 0; nt < 8; nt++) {
                const int cb = nbase + nt * 8;
                bf[nt][0] = __float_as_uint(Bs[(k + q)     * B_PAD + cb + g]);
                bf[nt][1] = __float_as_uint(Bs[(k + q + 4) * B_PAD + cb + g]);
            }
#pragma unroll
            for (int mt = 0; mt < 4; mt++)
#pragma unroll
                for (int nt = 0; nt < 8; nt++)
                    mma_tf32(acc[mt][nt], af[mt], bf[nt]);
        }
        __syncthreads();
    }

#pragma unroll
    for (int mt = 0; mt < 4; mt++) {
        const int rm = m0 + mbase + mt * 16 + g;
#pragma unroll
        for (int nt = 0; nt < 8; nt++) {
            const int cn = n0 + nbase + nt * 8 + 2 * q;
            float2 o0, o1;
            o0.x = acc[mt][nt][0] + bias[cn];
            o0.y = acc[mt][nt][1] + bias[cn + 1];
            o1.x = acc[mt][nt][2] + bias[cn];
            o1.y = acc[mt][nt][3] + bias[cn + 1];
            *(float2*)(C + (size_t)rm * N + cn)       = o0;
            *(float2*)(C + (size_t)(rm + 8) * N + cn) = o1;
        }
    }
}

// ================= rounding helper (weights) =================
__global__ void round_tf32_kernel(const float* __restrict__ in, float* __restrict__ out, int n4)
{
    int i = blockIdx.x * blockDim.x + threadIdx.x;
    if (i < n4) {
        float4 v = ((const float4*)in)[i];
        v.x = tf32r(v.x); v.y = tf32r(v.y); v.z = tf32r(v.z); v.w = tf32r(v.w);
        ((float4*)out)[i] = v;
    }
}

// ================= prepass 1: split Q (scaled by 0.125*log2e) and K =================
#define QSCALE 0.180336879091324521f   // 0.125 * log2(e)

__global__ void __launch_bounds__(256)
split_qk_kernel(const float* __restrict__ qkv,
                uint32_t* __restrict__ qhi, uint32_t* __restrict__ qlo,
                uint32_t* __restrict__ khi, uint32_t* __restrict__ klo)
{
    int i = blockIdx.x * blockDim.x + threadIdx.x;
    if (i >= M_TOT * EMB / 4) return;
    int bt = i >> 8;
    int c4 = i & 255;
    const float* p = qkv + (size_t)bt * C3 + c4 * 4;
    float4 qv = *(const float4*)p;
    float4 kv = *(const float4*)(p + EMB);
    uint32_t h0, l0, h1, l1;
    int w = bt * (EMB / 2) + c4 * 2;
    split2(qv.x * QSCALE, qv.y * QSCALE, h0, l0);
    split2(qv.z * QSCALE, qv.w * QSCALE, h1, l1);
    qhi[w] = h0; qhi[w + 1] = h1; qlo[w] = l0; qlo[w + 1] = l1;
    split2(kv.x, kv.y, h0, l0);
    split2(kv.z, kv.w, h1, l1);
    khi[w] = h0; khi[w + 1] = h1; klo[w] = l0; klo[w + 1] = l1;
}

// ================= prepass 2: transpose+split V per head =================
__global__ void __launch_bounds__(256)
transpose_v_kernel(const float* __restrict__ qkv,
                   uint32_t* __restrict__ vthi, uint32_t* __restrict__ vtlo)
{
    __shared__ float tile[64][65];
    const int s0 = blockIdx.x * 64;
    const int h  = blockIdx.y;
    const int b  = blockIdx.z;
    const int tid = threadIdx.x;

#pragma unroll
    for (int j = 0; j < 16; j++) {
        int idx = tid + j * 256;
        int r = idx >> 6, d = idx & 63;
        tile[r][d] = qkv[(size_t)(b * SEQ + s0 + r) * C3 + 2 * EMB + h * HDIM + d];
    }
    __syncthreads();

    const int wv = tid & 31;
    const int dq = tid >> 5;
#pragma unroll
    for (int j = 0; j < 8; j++) {
        int d = dq * 8 + j;
        float e = tile[2 * wv][d];
        float o = tile[2 * wv + 1][d];
        uint32_t whi, wlo;
        split2(e, o, whi, wlo);
        size_t wi = ((size_t)(b * NHEAD + h) * HDIM + d) * (SEQ / 2) + s0 / 2 + wv;
        vthi[wi] = whi;
        vtlo[wi] = wlo;
    }
}

// ================= tensor-core causal flash attention (bf16x3 + ldmatrix) =================
#define ROWW 36
#define ROWB 144                                  // bytes per smem row
#define Q_WORDS      (128 * ROWW)
#define KV_ARR_WORDS (64 * ROWW)                  // 2304 words = 9216 bytes
#define KV_ARR_BYTES (KV_ARR_WORDS * 4)
#define STAGE_WORDS  (4 * KV_ARR_WORDS)
#define STAGE_BYTES  (STAGE_WORDS * 4)            // 36864
#define ATT_SMEM_WORDS (2 * Q_WORDS + 2 * STAGE_WORDS)
#define ATT_SMEM_BYTES (ATT_SMEM_WORDS * 4)       // 110592

__global__ void __launch_bounds__(256)
attn_mma_kernel(const uint32_t* __restrict__ qhi, const uint32_t* __restrict__ qlo,
                const uint32_t* __restrict__ khi, const uint32_t* __restrict__ klo,
                const uint32_t* __restrict__ vthi, const uint32_t* __restrict__ vtlo,
                float* __restrict__ out)
{
    extern __shared__ uint32_t sbuf[];
    uint32_t* Qhi = sbuf;
    uint32_t* Qlo = Qhi + Q_WORDS;
    uint32_t* KV  = Qlo + Q_WORDS;

    const int qt   = (SEQ / 128 - 1) - blockIdx.x;
    const int h    = blockIdx.y;
    const int b    = blockIdx.z;
    const int tid  = threadIdx.x;
    const int w    = tid >> 5;
    const int lane = tid & 31;
    const int g    = lane >> 2;
    const int q    = lane & 3;

    const uint32_t kvS = smem_u32(KV);

    const char* qhiB = (const char*)qhi;
    const char* qloB = (const char*)qlo;
    const char* khiB = (const char*)khi;
    const char* kloB = (const char*)klo;
    const char* vhiB = (const char*)vthi;
    const char* vloB = (const char*)vtlo;
    const size_t qkRow0 = ((size_t)(b * SEQ) * EMB + h * HDIM) * 2;
    const size_t vRow0  = ((size_t)(b * NHEAD + h) * HDIM) * SEQ * 2;

    // ---- prologue: Q (both planes) + stage 0 K/V ----
    {
        const uint32_t qs_hi = smem_u32(Qhi);
        const uint32_t qs_lo = smem_u32(Qlo);
#pragma unroll
        for (int j = 0; j < 8; j++) {
            int rem = ((j & 3) << 8) | tid;
            int row = rem >> 3, ch = rem & 7;
            uint32_t sa = (j < 4 ? qs_hi : qs_lo) + row * ROWB + ch * 16;
            const char* gp = (j < 4 ? qhiB : qloB) +
                             qkRow0 + (size_t)(qt * 128 + row) * (EMB * 2) + ch * 16;
            cpa16(sa, gp);
        }
    }
    auto load_kv = [&](int kt, int s) {
        const uint32_t st = kvS + s * STAGE_BYTES;
#pragma unroll
        for (int j = 0; j < 8; j++) {
            int arr = j >> 1;
            int rem = ((j & 1) << 8) | tid;
            int row = rem >> 3, ch = rem & 7;
            uint32_t sa = st + arr * KV_ARR_BYTES + row * ROWB + ch * 16;
            const char* gp;
            if (arr == 0)
                gp = khiB + qkRow0 + (size_t)(kt * 64 + row) * (EMB * 2) + ch * 16;
            else if (arr == 1)
                gp = kloB + qkRow0 + (size_t)(kt * 64 + row) * (EMB * 2) + ch * 16;
            else if (arr == 2)
                gp = vhiB + vRow0 + (size_t)row * (SEQ * 2) + kt * 128 + ch * 16;
            else
                gp = vloB + vRow0 + (size_t)row * (SEQ * 2) + kt * 128 + ch * 16;
            cpa16(sa, gp);
        }
    };
    load_kv(0, 0);
    CP_COMMIT();

    float o[8][4];
#pragma unroll
    for (int t = 0; t < 8; t++)
#pragma unroll
        for (int v = 0; v < 4; v++) o[t][v] = 0.f;
    float m0 = -1e30f, m1 = -1e30f, l0 = 0.f, l1 = 0.f;

    const int rb   = w * 16;
    const int row0 = qt * 128 + rb + g;
    const int row1 = row0 + 8;
    const int kend = 2 * qt + 2;

    // ldmatrix per-lane address components
    // A-frag (Q, P): mat0 rows rb..rb+7 half0, mat1 rows rb+8..15 half0, mat2/3 = half1
    const uint32_t qlane = (rb + (lane & 7) + ((lane >> 3) & 1) * 8) * ROWB
                           + (lane >> 4) * 16;
    const uint32_t qhiA = smem_u32(Qhi) + qlane;
    const uint32_t qloA = smem_u32(Qlo) + qlane;
    // B-frag (K, V): mat0 rows(tile t) half0, mat1 rows t half1, mat2/3 tile t+1
    const uint32_t kvlane = ((lane & 7) + ((lane >> 4) << 3)) * ROWB
                            + ((lane >> 3) & 1) * 16;

    for (int kt = 0; kt < kend; kt++) {
        const int s = kt & 1;
        CP_WAIT(0);
        __syncthreads();
        if (kt + 1 < kend) { load_kv(kt + 1, s ^ 1); CP_COMMIT(); }

        if (kt * 64 <= qt * 128 + rb + 15) {
            const uint32_t stB  = kvS + s * STAGE_BYTES;
            const uint32_t khiA = stB + kvlane;
            const uint32_t kloA = khiA + KV_ARR_BYTES;
            const uint32_t vhiA = kloA + KV_ARR_BYTES;
            const uint32_t vloA = vhiA + KV_ARR_BYTES;

            float sc[8][4];
#pragma unroll
            for (int t = 0; t < 8; t++)
#pragma unroll
                for (int v = 0; v < 4; v++) sc[t][v] = 0.f;

#pragma unroll
            for (int j = 0; j < 4; j++) {
                uint32_t qh0, qh1, qh2, qh3, ql0, ql1, ql2, ql3;
                ldsm_x4(qh0, qh1, qh2, qh3, qhiA + j * 32);
                ldsm_x4(ql0, ql1, ql2, ql3, qloA + j * 32);
#pragma unroll
                for (int tp = 0; tp < 4; tp++) {
                    uint32_t k0, k1, k2, k3, e0, e1, e2, e3;
                    ldsm_x4(k0, k1, k2, k3, khiA + tp * (16 * ROWB) + j * 32);
                    ldsm_x4(e0, e1, e2, e3, kloA + tp * (16 * ROWB) + j * 32);
                    mma_bf16(sc[2 * tp],     qh0, qh1, qh2, qh3, k0, k1);
                    mma_bf16(sc[2 * tp],     qh0, qh1, qh2, qh3, e0, e1);
                    mma_bf16(sc[2 * tp],     ql0, ql1, ql2, ql3, k0, k1);
                    mma_bf16(sc[2 * tp + 1], qh0, qh1, qh2, qh3, k2, k3);
                    mma_bf16(sc[2 * tp + 1], qh0, qh1, qh2, qh3, e2, e3);
                    mma_bf16(sc[2 * tp + 1], ql0, ql1, ql2, ql3, k2, k3);
                }
            }

            if (kt >= 2 * qt) {
#pragma unroll
                for (int t = 0; t < 8; t++) {
                    int col = kt * 64 + 8 * t + 2 * q;
                    if (col     > row0) sc[t][0] = -1e30f;
                    if (col + 1 > row0) sc[t][1] = -1e30f;
                    if (col     > row1) sc[t][2] = -1e30f;
                    if (col + 1 > row1) sc[t][3] = -1e30f;
                }
            }

            float mx0 = -1e30f, mx1 = -1e30f;
#pragma unroll
            for (int t = 0; t < 8; t++) {
                mx0 = fmaxf(mx0, fmaxf(sc[t][0], sc[t][1]));
                mx1 = fmaxf(mx1, fmaxf(sc[t][2], sc[t][3]));
            }
            mx0 = fmaxf(mx0, __shfl_xor_sync(0xffffffffu, mx0, 1));
            mx0 = fmaxf(mx0, __shfl_xor_sync(0xffffffffu, mx0, 2));
            mx1 = fmaxf(mx1, __shfl_xor_sync(0xffffffffu, mx1, 1));
            mx1 = fmaxf(mx1, __shfl_xor_sync(0xffffffffu, mx1, 2));

            float mn0 = fmaxf(m0, mx0), mn1 = fmaxf(m1, mx1);
            float a0 = exp2f(m0 - mn0), a1 = exp2f(m1 - mn1);
            float sum0 = 0.f, sum1 = 0.f;
#pragma unroll
            for (int t = 0; t < 8; t++) {
                sc[t][0] = exp2f(sc[t][0] - mn0);
                sc[t][1] = exp2f(sc[t][1] - mn0);
                sc[t][2] = exp2f(sc[t][2] - mn1);
                sc[t][3] = exp2f(sc[t][3] - mn1);
                sum0 += sc[t][0] + sc[t][1];
                sum1 += sc[t][2] + sc[t][3];
            }
            sum0 += __shfl_xor_sync(0xffffffffu, sum0, 1);
            sum0 += __shfl_xor_sync(0xffffffffu, sum0, 2);
            sum1 += __shfl_xor_sync(0xffffffffu, sum1, 1);
            sum1 += __shfl_xor_sync(0xffffffffu, sum1, 2);
            l0 = l0 * a0 + sum0;
            l1 = l1 * a1 + sum1;
            m0 = mn0; m1 = mn1;
#pragma unroll
            for (int t = 0; t < 8; t++) {
                o[t][0] *= a0; o[t][1] *= a0;
                o[t][2] *= a1; o[t][3] *= a1;
            }

#pragma unroll
            for (int j = 0; j < 4; j++) {
                uint32_t ph0 = pack_bf16x2(sc[2*j][0],   sc[2*j][1]);
                uint32_t ph1 = pack_bf16x2(sc[2*j][2],   sc[2*j][3]);
                uint32_t ph2 = pack_bf16x2(sc[2*j+1][0], sc[2*j+1][1]);
                uint32_t ph3 = pack_bf16x2(sc[2*j+1][2], sc[2*j+1][3]);
                uint32_t pl0 = pack_bf16x2(sc[2*j][0]   - __uint_as_float(ph0 << 16),
                                           sc[2*j][1]   - __uint_as_float(ph0 & 0xFFFF0000u));
                uint32_t pl1 = pack_bf16x2(sc[2*j][2]   - __uint_as_float(ph1 << 16),
                                           sc[2*j][3]   - __uint_as_float(ph1 & 0xFFFF0000u));
                uint32_t pl2 = pack_bf16x2(sc[2*j+1][0] - __uint_as_float(ph2 << 16),
                                           sc[2*j+1][1] - __uint_as_float(ph2 & 0xFFFF0000u));
                uint32_t pl3 = pack_bf16x2(sc[2*j+1][2] - __uint_as_float(ph3 << 16),
                                           sc[2*j+1][3] - __uint_as_float(ph3 & 0xFFFF0000u));
#pragma unroll
                for (int tp = 0; tp < 4; tp++) {
                    uint32_t v0, v1, v2, v3, u0, u1, u2, u3;
                    ldsm_x4(v0, v1, v2, v3, vhiA + tp * (16 * ROWB) + j * 32);
                    ldsm_x4(u0, u1, u2, u3, vloA + tp * (16 * ROWB) + j * 32);
                    mma_bf16(o[2 * tp],     ph0, ph1, ph2, ph3, v0, v1);
                    mma_bf16(o[2 * tp],     ph0, ph1, ph2, ph3, u0, u1);
                    mma_bf16(o[2 * tp],     pl0, pl1, pl2, pl3, v0, v1);
                    mma_bf16(o[2 * tp + 1], ph0, ph1, ph2, ph3, v2, v3);
                    mma_bf16(o[2 * tp + 1], ph0, ph1, ph2, ph3, u2, u3);
                    mma_bf16(o[2 * tp + 1], pl0, pl1, pl2, pl3, v2, v3);
                }
            }
        }
        __syncthreads();
    }

    const float inv0 = 1.f / l0, inv1 = 1.f / l1;
    const size_t ob0 = ((size_t)b * SEQ + row0) * EMB + h * HDIM;
#pragma unroll
    for (int t = 0; t < 8; t++) {
        const int col = 8 * t + 2 * q;
        float2 w0, w1;
        w0.x = o[t][0] * inv0; w0.y = o[t][1] * inv0;
        w1.x = o[t][2] * inv1; w1.y = o[t][3] * inv1;
        *(float2*)(out + ob0 + col)            = w0;
        *(float2*)(out + ob0 + 8 * EMB + col)  = w1;
    }
}

// ---------------- launcher ----------------
extern "C" void kernel_launch(void* const* d_in, const int* in_sizes, int n_in,
                              void* d_out, int out_size)
{
    const float* x     = (const float*)d_in[0];
    const float* Wqkv  = (const float*)d_in[1];
    const float* bqkv  = (const float*)d_in[2];
    const float* Wproj = (const float*)d_in[3];
    const float* bproj = (const float*)d_in[4];
    float* out = (float*)d_out;

    float *qkv_p, *att_p, *wq_p, *wp_p;
    uint32_t *qhi_p, *qlo_p, *khi_p, *klo_p, *vhi_p, *vlo_p;
    cudaGetSymbolAddress((void**)&qkv_p, g_qkv);
    cudaGetSymbolAddress((void**)&att_p, g_att);
    cudaGetSymbolAddress((void**)&wq_p,  g_Wqkv_r);
    cudaGetSymbolAddress((void**)&wp_p,  g_Wproj_r);
    cudaGetSymbolAddress((void**)&qhi_p, g_qhi);
    cudaGetSymbolAddress((void**)&qlo_p, g_qlo);
    cudaGetSymbolAddress((void**)&khi_p, g_khi);
    cudaGetSymbolAddress((void**)&klo_p, g_klo);
    cudaGetSymbolAddress((void**)&vhi_p, g_vthi);
    cudaGetSymbolAddress((void**)&vlo_p, g_vtlo);

    cudaFuncSetAttribute(attn_mma_kernel, cudaFuncAttributeMaxDynamicSharedMemorySize,
                         (int)ATT_SMEM_BYTES);
    cudaFuncSetAttribute(gemm_tf32_mma, cudaFuncAttributeMaxDynamicSharedMemorySize,
                         (int)GEMM_SMEM_BYTES);

    // 0) tf32-round weights
    round_tf32_kernel<<<(EMB * C3 / 4 + 255) / 256, 256>>>(Wqkv, wq_p, EMB * C3 / 4);
    round_tf32_kernel<<<(EMB * EMB / 4 + 255) / 256, 256>>>(Wproj, wp_p, EMB * EMB / 4);

    // 1) qkv = x @ W_qkv + b_qkv
    gemm_tf32_mma<<<dim3(C3 / BN, M_TOT / BM), 256, GEMM_SMEM_BYTES>>>(x, wq_p, bqkv, qkv_p, C3);

    // 2a) pre-split Q/K, transpose+split V
    split_qk_kernel<<<(M_TOT * EMB / 4 + 255) / 256, 256>>>(qkv_p, qhi_p, qlo_p, khi_p, klo_p);
    transpose_v_kernel<<<dim3(SEQ / 64, NHEAD, BATCH), 256>>>(qkv_p, vhi_p, vlo_p);

    // 2b) causal attention
    attn_mma_kernel<<<dim3(SEQ / 128, NHEAD, BATCH), 256, ATT_SMEM_BYTES>>>(
        qhi_p, qlo_p, khi_p, klo_p, vhi_p, vlo_p, att_p);

    // 3) out = att @ W_proj + b_proj
    gemm_tf32_mma<<<dim3(EMB / BN, M_TOT / BM), 256, GEMM_SMEM_BYTES>>>(att_p, wp_p, bproj, out, EMB);
}

// round 8
// speedup vs baseline: 3.4445x; 1.0478x over previous
#include <cuda_runtime.h>
#include <cuda_bf16.h>
#include <math.h>
#include <stdint.h>

// ---------------- problem constants ----------------
#define BATCH  2
#define SEQ    2048
#define EMB    1024
#define NHEAD  16
#define HDIM   64
#define M_TOT  (BATCH * SEQ)       // 4096
#define C3     (3 * EMB)           // 3072
#define KDIM   1024

// ---------------- scratch ----------------
__device__ float    g_qkv[M_TOT * C3];        // 48 MB
__device__ float    g_att[M_TOT * EMB];       // 16 MB
__device__ float    g_Wqkv_r[EMB * C3];       // 12 MB
__device__ float    g_Wproj_r[EMB * EMB];     //  4 MB
__device__ uint32_t g_qhi[M_TOT * EMB / 2];   // Q*(0.125*log2e) hi
__device__ uint32_t g_qlo[M_TOT * EMB / 2];
__device__ uint32_t g_khi[M_TOT * EMB / 2];
__device__ uint32_t g_klo[M_TOT * EMB / 2];
__device__ uint32_t g_vthi[M_TOT * EMB / 2];  // V^T per head: [b][h][d][seq]
__device__ uint32_t g_vtlo[M_TOT * EMB / 2];

// ================= helpers =================
__device__ __forceinline__ uint32_t smem_u32(const void* p) {
    uint32_t a;
    asm("{ .reg .u64 t; cvta.to.shared.u64 t, %1; cvt.u32.u64 %0, t; }" : "=r"(a) : "l"(p));
    return a;
}
__device__ __forceinline__ float tf32r(float x) {
    uint32_t r;
    asm("cvt.rna.tf32.f32 %0, %1;" : "=r"(r) : "f"(x));
    return __uint_as_float(r);
}
__device__ __forceinline__ uint32_t tf32r_u(float x) {
    uint32_t r;
    asm("cvt.rna.tf32.f32 %0, %1;" : "=r"(r) : "f"(x));
    return r;
}
__device__ __forceinline__ void cpa16(uint32_t saddr, const void* g) {
    asm volatile("cp.async.cg.shared.global [%0], [%1], 16;" :: "r"(saddr), "l"(g));
}
#define CP_COMMIT()  asm volatile("cp.async.commit_group;")
#define CP_WAIT(n)   asm volatile("cp.async.wait_group %0;" :: "n"(n))

__device__ __forceinline__ void mma_tf32(float* d, const uint32_t* a, const uint32_t* b) {
    asm volatile(
        "mma.sync.aligned.m16n8k8.row.col.f32.tf32.tf32.f32 "
        "{%0,%1,%2,%3}, {%4,%5,%6,%7}, {%8,%9}, {%0,%1,%2,%3};"
        : "+f"(d[0]), "+f"(d[1]), "+f"(d[2]), "+f"(d[3])
        : "r"(a[0]), "r"(a[1]), "r"(a[2]), "r"(a[3]), "r"(b[0]), "r"(b[1]));
}
__device__ __forceinline__ void mma_bf16(float* d, uint32_t a0, uint32_t a1,
                                         uint32_t a2, uint32_t a3,
                                         uint32_t b0, uint32_t b1) {
    asm volatile(
        "mma.sync.aligned.m16n8k16.row.col.f32.bf16.bf16.f32 "
        "{%0,%1,%2,%3}, {%4,%5,%6,%7}, {%8,%9}, {%0,%1,%2,%3};"
        : "+f"(d[0]), "+f"(d[1]), "+f"(d[2]), "+f"(d[3])
        : "r"(a0), "r"(a1), "r"(a2), "r"(a3), "r"(b0), "r"(b1));
}
__device__ __forceinline__ void ldsm_x4(uint32_t& r0, uint32_t& r1, uint32_t& r2,
                                        uint32_t& r3, uint32_t addr) {
    asm volatile("ldmatrix.sync.aligned.m8n8.x4.shared.b16 {%0,%1,%2,%3}, [%4];"
                 : "=r"(r0), "=r"(r1), "=r"(r2), "=r"(r3) : "r"(addr));
}
__device__ __forceinline__ uint32_t pack_bf16x2(float e, float o) {
    uint32_t r;
    asm("cvt.rn.bf16x2.f32 %0, %1, %2;" : "=r"(r) : "f"(o), "f"(e));
    return r;
}
__device__ __forceinline__ void split2(float e, float o, uint32_t& whi, uint32_t& wlo) {
    whi = pack_bf16x2(e, o);
    float he = __uint_as_float(whi << 16);
    float ho = __uint_as_float(whi & 0xFFFF0000u);
    wlo = pack_bf16x2(e - he, o - ho);
}

// ================= tf32 mma.sync GEMM (round-5 proven) =================
#define BM 128
#define BN 256
#define BK 16
#define NIT (KDIM / BK)
#define A_PAD 20
#define B_PAD 264
#define A_STAGE (BM * A_PAD)
#define B_STAGE (BK * B_PAD)
#define GEMM_SMEM_BYTES (2 * (A_STAGE + B_STAGE) * 4)

__global__ void __launch_bounds__(256, 1)
gemm_tf32_mma(const float* __restrict__ A, const float* __restrict__ B,
              const float* __restrict__ bias, float* __restrict__ C, int N)
{
    extern __shared__ float gsm[];
    float* sA = gsm;
    float* sB = gsm + 2 * A_STAGE;

    const int tid   = threadIdx.x;
    const int wid   = tid >> 5;
    const int lane  = tid & 31;
    const int g     = lane >> 2;
    const int q     = lane & 3;
    const int warpM = wid >> 2;
    const int warpN = wid & 3;
    const int m0    = blockIdx.y * BM;
    const int n0    = blockIdx.x * BN;

    const uint32_t sA0 = smem_u32(sA);
    const uint32_t sB0 = smem_u32(sB);

    auto load_tiles = [&](int it, int s) {
        const int k0 = it * BK;
        const uint32_t aBase = sA0 + s * A_STAGE * 4;
        const uint32_t bBase = sB0 + s * B_STAGE * 4;
#pragma unroll
        for (int j = 0; j < 2; j++) {
            int c = tid + j * 256;
            int r = c >> 2, seg = c & 3;
            cpa16(aBase + (r * A_PAD + seg * 4) * 4,
                  A + (size_t)(m0 + r) * KDIM + k0 + seg * 4);
        }
#pragma unroll
        for (int j = 0; j < 4; j++) {
            int c = tid + j * 256;
            int r = c >> 6, seg = c & 63;
            cpa16(bBase + (r * B_PAD + seg * 4) * 4,
                  B + (size_t)(k0 + r) * N + n0 + seg * 4);
        }
        CP_COMMIT();
    };

    float acc[4][8][4];
#pragma unroll
    for (int i = 0; i < 4; i++)
#pragma unroll
        for (int j = 0; j < 8; j++)
#pragma unroll
            for (int v = 0; v < 4; v++) acc[i][j][v] = 0.f;

    load_tiles(0, 0);

    const int mbase = warpM * 64;
    const int nbase = warpN * 64;

    for (int it = 0; it < NIT; it++) {
        const int s = it & 1;
        if (it + 1 < NIT) { load_tiles(it + 1, s ^ 1); CP_WAIT(1); }
        else              { CP_WAIT(0); }
        __syncthreads();

        const float* As = sA + s * A_STAGE;
        const float* Bs = sB + s * B_STAGE;

#pragma unroll
        for (int kk = 0; kk < 2; kk++) {
            const int k = kk * 8;
            uint32_t af[4][4], bf[8][2];
#pragma unroll
            for (int mt = 0; mt < 4; mt++) {
                const int rb = mbase + mt * 16;
                af[mt][0] = tf32r_u(As[(rb + g)     * A_PAD + k + q]);
                af[mt][1] = tf32r_u(As[(rb + g + 8) * A_PAD + k + q]);
                af[mt][2] = tf32r_u(As[(rb + g)     * A_PAD + k + q + 4]);
                af[mt][3] = tf32r_u(As[(rb + g + 8) * A_PAD + k + q + 4]);
            }
#pragma unroll
            for (int nt = 0; nt < 8; nt++) {
                const int cb = nbase + nt * 8;
                bf[nt][0] = __float_as_uint(Bs[(k + q)     * B_PAD + cb + g]);
                bf[nt][1] = __float_as_uint(Bs[(k + q + 4) * B_PAD + cb + g]);
            }
#pragma unroll
            for (int mt = 0; mt < 4; mt++)
#pragma unroll
                for (int nt = 0; nt < 8; nt++)
                    mma_tf32(acc[mt][nt], af[mt], bf[nt]);
        }
        __syncthreads();
    }

#pragma unroll
    for (int mt = 0; mt < 4; mt++) {
        const int rm = m0 + mbase + mt * 16 + g;
#pragma unroll
        for (int nt = 0; nt < 8; nt++) {
            const int cn = n0 + nbase + nt * 8 + 2 * q;
            float2 o0, o1;
            o0.x = acc[mt][nt][0] + bias[cn];
            o0.y = acc[mt][nt][1] + bias[cn + 1];
            o1.x = acc[mt][nt][2] + bias[cn];
            o1.y = acc[mt][nt][3] + bias[cn + 1];
            *(float2*)(C + (size_t)rm * N + cn)       = o0;
            *(float2*)(C + (size_t)(rm + 8) * N + cn) = o1;
        }
    }
}

// ================= rounding helper (weights) =================
__global__ void round_tf32_kernel(const float* __restrict__ in, float* __restrict__ out, int n4)
{
    int i = blockIdx.x * blockDim.x + threadIdx.x;
    if (i < n4) {
        float4 v = ((const float4*)in)[i];
        v.x = tf32r(v.x); v.y = tf32r(v.y); v.z = tf32r(v.z); v.w = tf32r(v.w);
        ((float4*)out)[i] = v;
    }
}

// ================= prepass 1: split Q (scaled by 0.125*log2e) and K =================
#define QSCALE 0.180336879091324521f   // 0.125 * log2(e)

__global__ void __launch_bounds__(256)
split_qk_kernel(const float* __restrict__ qkv,
                uint32_t* __restrict__ qhi, uint32_t* __restrict__ qlo,
                uint32_t* __restrict__ khi, uint32_t* __restrict__ klo)
{
    int i = blockIdx.x * blockDim.x + threadIdx.x;
    if (i >= M_TOT * EMB / 4) return;
    int bt = i >> 8;
    int c4 = i & 255;
    const float* p = qkv + (size_t)bt * C3 + c4 * 4;
    float4 qv = *(const float4*)p;
    float4 kv = *(const float4*)(p + EMB);
    uint32_t h0, l0, h1, l1;
    int w = bt * (EMB / 2) + c4 * 2;
    split2(qv.x * QSCALE, qv.y * QSCALE, h0, l0);
    split2(qv.z * QSCALE, qv.w * QSCALE, h1, l1);
    qhi[w] = h0; qhi[w + 1] = h1; qlo[w] = l0; qlo[w + 1] = l1;
    split2(kv.x, kv.y, h0, l0);
    split2(kv.z, kv.w, h1, l1);
    khi[w] = h0; khi[w + 1] = h1; klo[w] = l0; klo[w + 1] = l1;
}

// ================= prepass 2: transpose+split V per head =================
__global__ void __launch_bounds__(256)
transpose_v_kernel(const float* __restrict__ qkv,
                   uint32_t* __restrict__ vthi, uint32_t* __restrict__ vtlo)
{
    __shared__ float tile[64][65];
    const int s0 = blockIdx.x * 64;
    const int h  = blockIdx.y;
    const int b  = blockIdx.z;
    const int tid = threadIdx.x;

#pragma unroll
    for (int j = 0; j < 16; j++) {
        int idx = tid + j * 256;
        int r = idx >> 6, d = idx & 63;
        tile[r][d] = qkv[(size_t)(b * SEQ + s0 + r) * C3 + 2 * EMB + h * HDIM + d];
    }
    __syncthreads();

    const int wv = tid & 31;
    const int dq = tid >> 5;
#pragma unroll
    for (int j = 0; j < 8; j++) {
        int d = dq * 8 + j;
        float e = tile[2 * wv][d];
        float o = tile[2 * wv + 1][d];
        uint32_t whi, wlo;
        split2(e, o, whi, wlo);
        size_t wi = ((size_t)(b * NHEAD + h) * HDIM + d) * (SEQ / 2) + s0 / 2 + wv;
        vthi[wi] = whi;
        vtlo[wi] = wlo;
    }
}

// ================= tensor-core causal flash attention =================
// 64-row Q tiles, 128 threads (4 warps), 2 CTAs/SM. bf16x3 + ldmatrix.
// Row-sum accumulated via ones-augmented PV mma (no per-iter sum reduce).
#define ROWW 36
#define ROWB 144
#define Q_WORDS      (64 * ROWW)                  // per plane
#define ONES_WORDS   (16 * ROWW)
#define KV_ARR_WORDS (64 * ROWW)
#define KV_ARR_BYTES (KV_ARR_WORDS * 4)
#define STAGE_WORDS  (4 * KV_ARR_WORDS)
#define STAGE_BYTES  (STAGE_WORDS * 4)
#define ATT_SMEM_WORDS (2 * Q_WORDS + ONES_WORDS + 2 * STAGE_WORDS)
#define ATT_SMEM_BYTES (ATT_SMEM_WORDS * 4)       // 94464

__global__ void __launch_bounds__(128, 2)
attn_mma_kernel(const uint32_t* __restrict__ qhi, const uint32_t* __restrict__ qlo,
                const uint32_t* __restrict__ khi, const uint32_t* __restrict__ klo,
                const uint32_t* __restrict__ vthi, const uint32_t* __restrict__ vtlo,
                float* __restrict__ out)
{
    extern __shared__ uint32_t sbuf[];
    uint32_t* Qhi  = sbuf;
    uint32_t* Qlo  = Qhi + Q_WORDS;
    uint32_t* Ones = Qlo + Q_WORDS;
    uint32_t* KV   = Ones + ONES_WORDS;

    const int qt   = (SEQ / 64 - 1) - blockIdx.x;
    const int h    = blockIdx.y;
    const int b    = blockIdx.z;
    const int tid  = threadIdx.x;
    const int w    = tid >> 5;
    const int lane = tid & 31;
    const int g    = lane >> 2;
    const int q    = lane & 3;

    const uint32_t kvS = smem_u32(KV);

    const char* qhiB = (const char*)qhi;
    const char* qloB = (const char*)qlo;
    const char* khiB = (const char*)khi;
    const char* kloB = (const char*)klo;
    const char* vhiB = (const char*)vthi;
    const char* vloB = (const char*)vtlo;
    const size_t qkRow0 = ((size_t)(b * SEQ) * EMB + h * HDIM) * 2;
    const size_t vRow0  = ((size_t)(b * NHEAD + h) * HDIM) * SEQ * 2;

    // ---- ones region: rows 0..7 = 1.0 bf16 pairs, rows 8..15 = 0 ----
    for (int i = tid; i < ONES_WORDS; i += 128)
        Ones[i] = (i < 8 * ROWW) ? 0x3F803F80u : 0u;

    // ---- prologue: Q (both planes) + stage 0 K/V ----
    {
        const uint32_t qs_hi = smem_u32(Qhi);
        const uint32_t qs_lo = smem_u32(Qlo);
#pragma unroll
        for (int j = 0; j < 8; j++) {
            int idx = j * 128 + tid;                  // 0..1023
            int plane = idx >> 9;
            int rem = idx & 511;
            int row = rem >> 3, ch = rem & 7;
            uint32_t sa = (plane ? qs_lo : qs_hi) + row * ROWB + ch * 16;
            const char* gp = (plane ? qloB : qhiB) +
                             qkRow0 + (size_t)(qt * 64 + row) * (EMB * 2) + ch * 16;
            cpa16(sa, gp);
        }
    }
    auto load_kv = [&](int kt, int s) {
        const uint32_t st = kvS + s * STAGE_BYTES;
#pragma unroll
        for (int j = 0; j < 16; j++) {
            int idx = j * 128 + tid;                  // 0..2047
            int arr = idx >> 9;
            int rem = idx & 511;
            int row = rem >> 3, ch = rem & 7;
            uint32_t sa = st + arr * KV_ARR_BYTES + row * ROWB + ch * 16;
            const char* gp;
            if (arr == 0)
                gp = khiB + qkRow0 + (size_t)(kt * 64 + row) * (EMB * 2) + ch * 16;
            else if (arr == 1)
                gp = kloB + qkRow0 + (size_t)(kt * 64 + row) * (EMB * 2) + ch * 16;
            else if (arr == 2)
                gp = vhiB + vRow0 + (size_t)row * (SEQ * 2) + kt * 128 + ch * 16;
            else
                gp = vloB + vRow0 + (size_t)row * (SEQ * 2) + kt * 128 + ch * 16;
            cpa16(sa, gp);
        }
    };
    load_kv(0, 0);
    CP_COMMIT();
    __syncthreads();   // ones region visible

    // constant ones B-fragment (k=16 keys x n=8, rows>=8 are zero)
    const uint32_t kvlane = ((lane & 7) + ((lane >> 4) << 3)) * ROWB
                            + ((lane >> 3) & 1) * 16;
    uint32_t on0, on1, on2, on3;
    ldsm_x4(on0, on1, on2, on3, smem_u32(Ones) + kvlane);
    (void)on2; (void)on3;

    float o[8][4], ol[4];
#pragma unroll
    for (int t = 0; t < 8; t++)
#pragma unroll
        for (int v = 0; v < 4; v++) o[t][v] = 0.f;
#pragma unroll
    for (int v = 0; v < 4; v++) ol[v] = 0.f;
    float m0 = -1e30f, m1 = -1e30f;

    const int rb   = w * 16;
    const int row0 = qt * 64 + rb + g;
    const int row1 = row0 + 8;
    const int kend = qt + 1;

    const uint32_t qlane = (rb + (lane & 7) + ((lane >> 3) & 1) * 8) * ROWB
                           + (lane >> 4) * 16;
    const uint32_t qhiA = smem_u32(Qhi) + qlane;
    const uint32_t qloA = smem_u32(Qlo) + qlane;

    for (int kt = 0; kt < kend; kt++) {
        const int s = kt & 1;
        CP_WAIT(0);
        __syncthreads();
        if (kt + 1 < kend) { load_kv(kt + 1, s ^ 1); CP_COMMIT(); }

        const uint32_t stB  = kvS + s * STAGE_BYTES;
        const uint32_t khiA = stB + kvlane;
        const uint32_t kloA = khiA + KV_ARR_BYTES;
        const uint32_t vhiA = kloA + KV_ARR_BYTES;
        const uint32_t vloA = vhiA + KV_ARR_BYTES;

        float sc[8][4];
#pragma unroll
        for (int t = 0; t < 8; t++)
#pragma unroll
            for (int v = 0; v < 4; v++) sc[t][v] = 0.f;

#pragma unroll
        for (int j = 0; j < 4; j++) {
            uint32_t qh0, qh1, qh2, qh3, ql0, ql1, ql2, ql3;
            ldsm_x4(qh0, qh1, qh2, qh3, qhiA + j * 32);
            ldsm_x4(ql0, ql1, ql2, ql3, qloA + j * 32);
#pragma unroll
            for (int tp = 0; tp < 4; tp++) {
                uint32_t k0, k1, k2, k3, e0, e1, e2, e3;
                ldsm_x4(k0, k1, k2, k3, khiA + tp * (16 * ROWB) + j * 32);
                ldsm_x4(e0, e1, e2, e3, kloA + tp * (16 * ROWB) + j * 32);
                mma_bf16(sc[2 * tp],     qh0, qh1, qh2, qh3, k0, k1);
                mma_bf16(sc[2 * tp],     qh0, qh1, qh2, qh3, e0, e1);
                mma_bf16(sc[2 * tp],     ql0, ql1, ql2, ql3, k0, k1);
                mma_bf16(sc[2 * tp + 1], qh0, qh1, qh2, qh3, k2, k3);
                mma_bf16(sc[2 * tp + 1], qh0, qh1, qh2, qh3, e2, e3);
                mma_bf16(sc[2 * tp + 1], ql0, ql1, ql2, ql3, k2, k3);
            }
        }

        if (kt == qt) {      // diagonal tile mask
#pragma unroll
            for (int t = 0; t < 8; t++) {
                int col = kt * 64 + 8 * t + 2 * q;
                if (col     > row0) sc[t][0] = -1e30f;
                if (col + 1 > row0) sc[t][1] = -1e30f;
                if (col     > row1) sc[t][2] = -1e30f;
                if (col + 1 > row1) sc[t][3] = -1e30f;
            }
        }

        float mx0 = -1e30f, mx1 = -1e30f;
#pragma unroll
        for (int t = 0; t < 8; t++) {
            mx0 = fmaxf(mx0, fmaxf(sc[t][0], sc[t][1]));
            mx1 = fmaxf(mx1, fmaxf(sc[t][2], sc[t][3]));
        }
        mx0 = fmaxf(mx0, __shfl_xor_sync(0xffffffffu, mx0, 1));
        mx0 = fmaxf(mx0, __shfl_xor_sync(0xffffffffu, mx0, 2));
        mx1 = fmaxf(mx1, __shfl_xor_sync(0xffffffffu, mx1, 1));
        mx1 = fmaxf(mx1, __shfl_xor_sync(0xffffffffu, mx1, 2));

        float mn0 = fmaxf(m0, mx0), mn1 = fmaxf(m1, mx1);
        float a0 = exp2f(m0 - mn0), a1 = exp2f(m1 - mn1);
        m0 = mn0; m1 = mn1;
#pragma unroll
        for (int t = 0; t < 8; t++) {
            sc[t][0] = exp2f(sc[t][0] - mn0);
            sc[t][1] = exp2f(sc[t][1] - mn0);
            sc[t][2] = exp2f(sc[t][2] - mn1);
            sc[t][3] = exp2f(sc[t][3] - mn1);
        }
#pragma unroll
        for (int t = 0; t < 8; t++) {
            o[t][0] *= a0; o[t][1] *= a0;
            o[t][2] *= a1; o[t][3] *= a1;
        }
        ol[0] *= a0; ol[1] *= a0; ol[2] *= a1; ol[3] *= a1;

#pragma unroll
        for (int j = 0; j < 4; j++) {
            uint32_t ph0 = pack_bf16x2(sc[2*j][0],   sc[2*j][1]);
            uint32_t ph1 = pack_bf16x2(sc[2*j][2],   sc[2*j][3]);
            uint32_t ph2 = pack_bf16x2(sc[2*j+1][0], sc[2*j+1][1]);
            uint32_t ph3 = pack_bf16x2(sc[2*j+1][2], sc[2*j+1][3]);
            uint32_t pl0 = pack_bf16x2(sc[2*j][0]   - __uint_as_float(ph0 << 16),
                                       sc[2*j][1]   - __uint_as_float(ph0 & 0xFFFF0000u));
            uint32_t pl1 = pack_bf16x2(sc[2*j][2]   - __uint_as_float(ph1 << 16),
                                       sc[2*j][3]   - __uint_as_float(ph1 & 0xFFFF0000u));
            uint32_t pl2 = pack_bf16x2(sc[2*j+1][0] - __uint_as_float(ph2 << 16),
                                       sc[2*j+1][1] - __uint_as_float(ph2 & 0xFFFF0000u));
            uint32_t pl3 = pack_bf16x2(sc[2*j+1][2] - __uint_as_float(ph3 << 16),
                                       sc[2*j+1][3] - __uint_as_float(ph3 & 0xFFFF0000u));
            // row-sum via ones matrix (accumulates softmax denominator)
            mma_bf16(ol, ph0, ph1, ph2, ph3, on0, on1);
            mma_bf16(ol, pl0, pl1, pl2, pl3, on0, on1);
#pragma unroll
            for (int tp = 0; tp < 4; tp++) {
                uint32_t v0, v1, v2, v3, u0, u1, u2, u3;
                ldsm_x4(v0, v1, v2, v3, vhiA + tp * (16 * ROWB) + j * 32);
                ldsm_x4(u0, u1, u2, u3, vloA + tp * (16 * ROWB) + j * 32);
                mma_bf16(o[2 * tp],     ph0, ph1, ph2, ph3, v0, v1);
                mma_bf16(o[2 * tp],     ph0, ph1, ph2, ph3, u0, u1);
                mma_bf16(o[2 * tp],     pl0, pl1, pl2, pl3, v0, v1);
                mma_bf16(o[2 * tp + 1], ph0, ph1, ph2, ph3, v2, v3);
                mma_bf16(o[2 * tp + 1], ph0, ph1, ph2, ph3, u2, u3);
                mma_bf16(o[2 * tp + 1], pl0, pl1, pl2, pl3, v2, v3);
            }
        }
        __syncthreads();
    }

    const float inv0 = 1.f / ol[0], inv1 = 1.f / ol[2];
    const size_t ob0 = ((size_t)b * SEQ + row0) * EMB + h * HDIM;
#pragma unroll
    for (int t = 0; t < 8; t++) {
        const int col = 8 * t + 2 * q;
        float2 w0, w1;
        w0.x = o[t][0] * inv0; w0.y = o[t][1] * inv0;
        w1.x = o[t][2] * inv1; w1.y = o[t][3] * inv1;
        *(float2*)(out + ob0 + col)            = w0;
        *(float2*)(out + ob0 + 8 * EMB + col)  = w1;
    }
}

// ---------------- launcher ----------------
extern "C" void kernel_launch(void* const* d_in, const int* in_sizes, int n_in,
                              void* d_out, int out_size)
{
    const float* x     = (const float*)d_in[0];
    const float* Wqkv  = (const float*)d_in[1];
    const float* bqkv  = (const float*)d_in[2];
    const float* Wproj = (const float*)d_in[3];
    const float* bproj = (const float*)d_in[4];
    float* out = (float*)d_out;

    float *qkv_p, *att_p, *wq_p, *wp_p;
    uint32_t *qhi_p, *qlo_p, *khi_p, *klo_p, *vhi_p, *vlo_p;
    cudaGetSymbolAddress((void**)&qkv_p, g_qkv);
    cudaGetSymbolAddress((void**)&att_p, g_att);
    cudaGetSymbolAddress((void**)&wq_p,  g_Wqkv_r);
    cudaGetSymbolAddress((void**)&wp_p,  g_Wproj_r);
    cudaGetSymbolAddress((void**)&qhi_p, g_qhi);
    cudaGetSymbolAddress((void**)&qlo_p, g_qlo);
    cudaGetSymbolAddress((void**)&khi_p, g_khi);
    cudaGetSymbolAddress((void**)&klo_p, g_klo);
    cudaGetSymbolAddress((void**)&vhi_p, g_vthi);
    cudaGetSymbolAddress((void**)&vlo_p, g_vtlo);

    cudaFuncSetAttribute(attn_mma_kernel, cudaFuncAttributeMaxDynamicSharedMemorySize,
                         (int)ATT_SMEM_BYTES);
    cudaFuncSetAttribute(gemm_tf32_mma, cudaFuncAttributeMaxDynamicSharedMemorySize,
                         (int)GEMM_SMEM_BYTES);

    // 0) tf32-round weights
    round_tf32_kernel<<<(EMB * C3 / 4 + 255) / 256, 256>>>(Wqkv, wq_p, EMB * C3 / 4);
    round_tf32_kernel<<<(EMB * EMB / 4 + 255) / 256, 256>>>(Wproj, wp_p, EMB * EMB / 4);

    // 1) qkv = x @ W_qkv + b_qkv
    gemm_tf32_mma<<<dim3(C3 / BN, M_TOT / BM), 256, GEMM_SMEM_BYTES>>>(x, wq_p, bqkv, qkv_p, C3);

    // 2a) pre-split Q/K, transpose+split V
    split_qk_kernel<<<(M_TOT * EMB / 4 + 255) / 256, 256>>>(qkv_p, qhi_p, qlo_p, khi_p, klo_p);
    transpose_v_kernel<<<dim3(SEQ / 64, NHEAD, BATCH), 256>>>(qkv_p, vhi_p, vlo_p);

    // 2b) causal attention
    attn_mma_kernel<<<dim3(SEQ / 64, NHEAD, BATCH), 128, ATT_SMEM_BYTES>>>(
        qhi_p, qlo_p, khi_p, klo_p, vhi_p, vlo_p, att_p);

    // 3) out = att @ W_proj + b_proj
    gemm_tf32_mma<<<dim3(EMB / BN, M_TOT / BM), 256, GEMM_SMEM_BYTES>>>(att_p, wp_p, bproj, out, EMB);
}